// round 11
// baseline (speedup 1.0000x reference)
#include <cuda_runtime.h>
#include <cuda_fp16.h>
#include <cstdint>

#define W 128
#define G 64
#define MAXN 100000
#define MAXE 625000
#define EPS 1e-5f

// ---------------- scratch (static device globals; zero-initialized) ----------
__device__ __half g_xnh[MAXN * W];
__device__ __half g_aggh[MAXN * W];
__device__ __half g_h1h[MAXN * W];
__device__ __half g_wh[2 * 128 * 256];
__device__ float g_sum[G * W];        // self-cleaned by finalize
__device__ float g_sumsq[G * W];      // self-cleaned by finalize
__device__ float g_cnt[G];            // self-cleaned by finalize
__device__ float g_alpha[G * W];
__device__ float g_beta[G * W];
__device__ int   g_deg[MAXN];         // self-cleaned by scan3
__device__ int   g_base[MAXN + 4];
__device__ int   g_cur[MAXN];         // self-cleaned by gather
__device__ int2  g_elist[MAXE];
__device__ int   g_bsum[64];

// ---------------- PTX helpers (sm_80/90 baseline only) -----------------------
__device__ __forceinline__ uint32_t smem_u32(const void* p) {
    uint32_t a;
    asm("{ .reg .u64 t; cvta.to.shared.u64 t, %1; cvt.u32.u64 %0, t; }"
        : "=r"(a) : "l"(p));
    return a;
}
__device__ __forceinline__ void ldsm4(uint4& r, uint32_t addr) {
    asm volatile("ldmatrix.sync.aligned.m8n8.x4.shared.b16 {%0,%1,%2,%3}, [%4];"
                 : "=r"(r.x), "=r"(r.y), "=r"(r.z), "=r"(r.w) : "r"(addr));
}
__device__ __forceinline__ void mma16816(float* d, const uint4& a,
                                         uint32_t b0, uint32_t b1) {
    asm volatile(
        "mma.sync.aligned.m16n8k16.row.col.f32.f16.f16.f32 "
        "{%0,%1,%2,%3}, {%4,%5,%6,%7}, {%8,%9}, {%0,%1,%2,%3};"
        : "+f"(d[0]), "+f"(d[1]), "+f"(d[2]), "+f"(d[3])
        : "r"(a.x), "r"(a.y), "r"(a.z), "r"(a.w), "r"(b0), "r"(b1));
}
__device__ __forceinline__ void cp16(uint32_t dst, const void* src, bool pred) {
    int sz = pred ? 16 : 0;
    asm volatile("cp.async.cg.shared.global [%0], [%1], 16, %2;"
                 :: "r"(dst), "l"(src), "r"(sz) : "memory");
}
#define CP_COMMIT() asm volatile("cp.async.commit_group;" ::: "memory")
#define CP_WAIT(N)  asm volatile("cp.async.wait_group %0;" :: "n"(N) : "memory")

// ================= K1: stats || hist || wprep (grid-partitioned) =============
__global__ __launch_bounds__(256) void k1_kernel(
    const float* __restrict__ x, const int* __restrict__ bmap, int n,
    const int* __restrict__ dst, int E,
    const float* __restrict__ Wr1, const float* __restrict__ Wo1,
    const float* __restrict__ Wr2, const float* __restrict__ Wo2,
    int nbS, int nbH)
{
    int b = blockIdx.x, tid = threadIdx.x;
    if (b < nbS) {
        int f = tid & 127, sub = tid >> 7;
        int n0 = b * 256 + sub * 128;
        if (n0 >= n) return;
        int n1 = min(n0 + 128, n);
        float s = 0.f, ss = 0.f;
        int curg = __ldg(bmap + n0);
        #pragma unroll 1
        for (int r = n0; r < n1; r++) {
            int g = __ldg(bmap + r);
            if (g != curg) {
                atomicAdd(&g_sum[curg * W + f], s);
                atomicAdd(&g_sumsq[curg * W + f], ss);
                s = 0.f; ss = 0.f; curg = g;
            }
            float v = x[(size_t)r * W + f];
            s += v; ss += v * v;
        }
        atomicAdd(&g_sum[curg * W + f], s);
        atomicAdd(&g_sumsq[curg * W + f], ss);
        if (f == 0) {
            int cg = __ldg(bmap + n0), rs = n0;
            for (int r = n0; r < n1; r++) {
                int g = __ldg(bmap + r);
                if (g != cg) {
                    atomicAdd(&g_cnt[cg], (float)(r - rs));
                    cg = g; rs = r;
                }
            }
            atomicAdd(&g_cnt[cg], (float)(n1 - rs));
        }
    } else if (b < nbS + nbH) {
        int i4 = (b - nbS) * 256 + tid;
        int e = i4 * 4;
        if (e + 3 < E) {
            int4 d = __ldg((const int4*)dst + i4);
            atomicAdd(&g_deg[d.x], 1);
            atomicAdd(&g_deg[d.y], 1);
            atomicAdd(&g_deg[d.z], 1);
            atomicAdd(&g_deg[d.w], 1);
        } else {
            for (int j2 = 0; j2 < 4; j2++)
                if (e + j2 < E) atomicAdd(&g_deg[__ldg(dst + e + j2)], 1);
        }
    } else {
        int idx = (b - nbS - nbH) * 256 + tid;
        int conv = idx >> 14;
        int rem  = idx & 16383;
        int row  = rem >> 7;
        int c2   = rem & 127;
        const float* Wr = conv ? Wr2 : Wr1;
        const float* Wo = conv ? Wo2 : Wo1;
        const float* s = (c2 < 64) ? (Wr + row * 128 + c2 * 2)
                                   : (Wo + row * 128 + (c2 - 64) * 2);
        float2 v = *(const float2*)s;
        ((__half2*)(g_wh + (size_t)conv * 128 * 256 + row * 256))[c2] =
            __floats2half2_rn(v.x, v.y);
    }
}

// ================= K2: finalize || scan1 =====================================
__global__ __launch_bounds__(256) void k2_kernel(
    const float* __restrict__ gnw, const float* __restrict__ gnb,
    const float* __restrict__ msc, int n4, int nbF)
{
    int b = blockIdx.x, tid = threadIdx.x, lane = tid & 31, wid = tid >> 5;
    if (b < nbF) {
        int idx = b * 256 + tid;
        int g = idx >> 7, f = idx & 127;
        float cnt  = g_cnt[g];
        float inv  = (cnt > 0.f) ? (1.f / cnt) : 0.f;
        float mean = g_sum[idx] * inv;
        float q    = g_sumsq[idx] * inv;
        g_sum[idx] = 0.f;
        g_sumsq[idx] = 0.f;
        float m    = __ldg(msc + f);
        float var  = q - mean * mean * m * (2.f - m);
        float istd = rsqrtf(var + EPS);
        float a    = __ldg(gnw + f) * istd;
        g_alpha[idx] = a;
        g_beta[idx]  = __ldg(gnb + f) - a * m * mean;
        __syncthreads();
        if (f == 0) g_cnt[g] = 0.f;
    } else {
        __shared__ int wS[8];
        int sb = b - nbF;
        const int4* dp = (const int4*)g_deg;
        int i4 = sb * 1024 + tid * 4;
        int s = 0;
        #pragma unroll
        for (int j2 = 0; j2 < 4; j2++) {
            if (i4 + j2 < n4) {
                int4 v = dp[i4 + j2];
                s += v.x + v.y + v.z + v.w;
            }
        }
        #pragma unroll
        for (int o = 16; o > 0; o >>= 1) s += __shfl_down_sync(~0u, s, o);
        if (lane == 0) wS[wid] = s;
        __syncthreads();
        if (tid == 0) {
            int t = 0;
            #pragma unroll
            for (int k = 0; k < 8; k++) t += wS[k];
            g_bsum[sb] = t;
        }
    }
}

// ================= K3: scan3 (with inline scan2 over g_bsum) =================
__global__ __launch_bounds__(256) void k3_kernel(int n4, int nscan, int n)
{
    __shared__ int wS[8];
    __shared__ int boff;
    int b = blockIdx.x, tid = threadIdx.x, lane = tid & 31, wid = tid >> 5;
    if (tid == 0) {
        int run = 0;
        for (int i = 0; i < b; i++) run += g_bsum[i];
        boff = run;
        if (b == 0) {
            int tot = 0;
            for (int i = 0; i < nscan; i++) tot += g_bsum[i];
            g_base[n] = tot;
        }
    }
    int4* dp = (int4*)g_deg;
    int i4 = b * 1024 + tid * 4;
    int4 v[4];
    int s = 0;
    #pragma unroll
    for (int j2 = 0; j2 < 4; j2++) {
        v[j2] = make_int4(0, 0, 0, 0);
        if (i4 + j2 < n4) {
            v[j2] = dp[i4 + j2];
            dp[i4 + j2] = make_int4(0, 0, 0, 0);
        }
        s += v[j2].x + v[j2].y + v[j2].z + v[j2].w;
    }
    int x = s;
    #pragma unroll
    for (int o = 1; o < 32; o <<= 1) {
        int y = __shfl_up_sync(~0u, x, o);
        if (lane >= o) x += y;
    }
    if (lane == 31) wS[wid] = x;
    __syncthreads();
    int woff = 0;
    #pragma unroll
    for (int k = 0; k < 8; k++)
        if (k < wid) woff += wS[k];
    int run = boff + woff + x - s;
    int4* bp = (int4*)g_base;
    #pragma unroll
    for (int j2 = 0; j2 < 4; j2++) {
        if (i4 + j2 < n4) {
            int4 o;
            o.x = run; run += v[j2].x;
            o.y = run; run += v[j2].y;
            o.z = run; run += v[j2].z;
            o.w = run; run += v[j2].w;
            bp[i4 + j2] = o;
        }
    }
}

// ================= K4: place || norm =========================================
__global__ __launch_bounds__(256) void k4_kernel(
    const int* __restrict__ src, const int* __restrict__ dst,
    const float* __restrict__ ew, int E,
    const float4* __restrict__ x, const int* __restrict__ bmap, int total4,
    int nbP)
{
    int b = blockIdx.x, tid = threadIdx.x;
    if (b < nbP) {
        int i4 = b * 256 + tid;
        int e = i4 * 4;
        if (e + 3 < E) {
            int4 sv = __ldg((const int4*)src + i4);
            int4 dv = __ldg((const int4*)dst + i4);
            float4 wv = __ldg((const float4*)ew + i4);
            int p;
            p = g_base[dv.x] + atomicAdd(&g_cur[dv.x], 1);
            g_elist[p] = make_int2(sv.x, __float_as_int(wv.x));
            p = g_base[dv.y] + atomicAdd(&g_cur[dv.y], 1);
            g_elist[p] = make_int2(sv.y, __float_as_int(wv.y));
            p = g_base[dv.z] + atomicAdd(&g_cur[dv.z], 1);
            g_elist[p] = make_int2(sv.z, __float_as_int(wv.z));
            p = g_base[dv.w] + atomicAdd(&g_cur[dv.w], 1);
            g_elist[p] = make_int2(sv.w, __float_as_int(wv.w));
        } else {
            for (int j2 = 0; j2 < 4; j2++) {
                int ee = e + j2;
                if (ee < E) {
                    int d = __ldg(dst + ee);
                    int p = g_base[d] + atomicAdd(&g_cur[d], 1);
                    g_elist[p] = make_int2(__ldg(src + ee),
                                           __float_as_int(__ldg(ew + ee)));
                }
            }
        }
    } else {
        int idx = (b - nbP) * 256 + tid;
        if (idx >= total4) return;
        int r = idx >> 5, c = idx & 31;
        int g = __ldg(bmap + r);
        float4 xv = __ldg(x + idx);
        float4 a = ((const float4*)g_alpha)[g * 32 + c];
        float4 bb = ((const float4*)g_beta)[g * 32 + c];
        float ox = fmaf(a.x, xv.x, bb.x);
        float oy = fmaf(a.y, xv.y, bb.y);
        float oz = fmaf(a.z, xv.z, bb.z);
        float ow = fmaf(a.w, xv.w, bb.w);
        uint2 o;
        *(__half2*)&o.x = __floats2half2_rn(ox, oy);
        *(__half2*)&o.y = __floats2half2_rn(oz, ow);
        ((uint2*)g_xnh)[idx] = o;
    }
}

// ---------------- gather (fp16 rows, fp32 accumulate) ------------------------
__global__ __launch_bounds__(256) void gather_kernel(
    const uint2* __restrict__ in, uint2* __restrict__ agg, int n)
{
    int warp = (blockIdx.x * 256 + threadIdx.x) >> 5;
    if (warp >= n) return;
    int c = threadIdx.x & 31;
    int b0 = g_base[warp], b1 = g_base[warp + 1];
    if (c == 0) g_cur[warp] = 0;
    float4 acc = make_float4(0.f, 0.f, 0.f, 0.f);
    int e = b0;
    #pragma unroll 1
    for (; e + 2 <= b1; e += 2) {
        int2 s0 = __ldg(&g_elist[e]);
        int2 s1 = __ldg(&g_elist[e + 1]);
        uint2 v0 = __ldg(in + (size_t)s0.x * 32 + c);
        uint2 v1 = __ldg(in + (size_t)s1.x * 32 + c);
        float w0 = __int_as_float(s0.y), w1 = __int_as_float(s1.y);
        float2 a0 = __half22float2(*(__half2*)&v0.x);
        float2 a1 = __half22float2(*(__half2*)&v0.y);
        acc.x = fmaf(w0, a0.x, acc.x); acc.y = fmaf(w0, a0.y, acc.y);
        acc.z = fmaf(w0, a1.x, acc.z); acc.w = fmaf(w0, a1.y, acc.w);
        float2 b0f = __half22float2(*(__half2*)&v1.x);
        float2 b1f = __half22float2(*(__half2*)&v1.y);
        acc.x = fmaf(w1, b0f.x, acc.x); acc.y = fmaf(w1, b0f.y, acc.y);
        acc.z = fmaf(w1, b1f.x, acc.z); acc.w = fmaf(w1, b1f.y, acc.w);
    }
    if (e < b1) {
        int2 s0 = __ldg(&g_elist[e]);
        uint2 v0 = __ldg(in + (size_t)s0.x * 32 + c);
        float w0 = __int_as_float(s0.y);
        float2 a0 = __half22float2(*(__half2*)&v0.x);
        float2 a1 = __half22float2(*(__half2*)&v0.y);
        acc.x = fmaf(w0, a0.x, acc.x); acc.y = fmaf(w0, a0.y, acc.y);
        acc.z = fmaf(w0, a1.x, acc.z); acc.w = fmaf(w0, a1.y, acc.w);
    }
    uint2 o;
    *(__half2*)&o.x = __floats2half2_rn(acc.x, acc.y);
    *(__half2*)&o.y = __floats2half2_rn(acc.z, acc.w);
    agg[(size_t)warp * 32 + c] = o;
}

// ---------------- persistent fp16 warp-MMA GEMM ------------------------------
// Grid = min(148, nTiles); each CTA loops tiles bid, bid+grid, ... Weights
// (64KB) staged ONCE per CTA. A chunks (16KB) pipelined across tile
// boundaries: global chunk counter gc, buffers mod 3, 2-deep wait_group(1).
// Tile = 128 rows; warp = 32 rows x 64 cols; combined K=256 (4 chunks):
// chunks 0-1 = agg (vs Wrel), 2-3 = root input (vs Wroot).
#define GB_A0   1024
#define GB_W    (GB_A0 + 3 * 16384)
#define GB_SMEM (GB_W + 65536)

__device__ __forceinline__ void cpA(uint32_t sbase, int buf, int tid, int r0,
                                    int n, int c,
                                    const __half* __restrict__ Arel,
                                    const __half* __restrict__ Aroot)
{
    const char* As = (const char*)((c < 2) ? Arel : Aroot);
    int off = (c & 1) * 128;
    #pragma unroll
    for (int i = 0; i < 4; i++) {
        int q = tid + i * 256;
        int row = q >> 3, u = q & 7;
        int gr = r0 + row;
        cp16(sbase + GB_A0 + buf * 16384 + row * 128 + (((u ^ (row & 7)) & 7) << 4),
             As + (size_t)gr * 256 + off + u * 16, gr < n);
    }
}

template <int MODE>
__global__ __launch_bounds__(256) void gemm_h_kernel(
    const __half* __restrict__ Arel, const __half* __restrict__ Aroot,
    const __half* __restrict__ wh, const float* __restrict__ brel,
    const float* __restrict__ resid, void* __restrict__ outv, int n,
    int nTiles)
{
    extern __shared__ char smem[];
    uint32_t sbase = smem_u32(smem);
    int tid = threadIdx.x, wid = tid >> 5, lane = tid & 31;
    int wm = wid & 3, wn = wid >> 2;
    int bid = blockIdx.x, stride = gridDim.x;

    int myTiles = (nTiles - bid + stride - 1) / stride;
    if (myTiles <= 0) return;
    int total = myTiles * 4;

    if (tid < 128) ((float*)smem)[tid] = __ldg(brel + tid);

    // group 0: weights (staged ONCE) + A chunk 0 of first tile
    #pragma unroll
    for (int i = 0; i < 16; i++) {
        int q = tid + i * 256;
        int row = q >> 5, uu = q & 31;
        int phys = (uu & 0x18) | ((uu ^ row) & 7);
        cp16(sbase + GB_W + row * 512 + phys * 16,
             (const char*)wh + (size_t)row * 512 + uu * 16, true);
    }
    cpA(sbase, 0, tid, bid * 128, n, 0, Arel, Aroot);
    CP_COMMIT();
    if (total > 1) {
        cpA(sbase, 1, tid, bid * 128, n, 1, Arel, Aroot);
        CP_COMMIT();
    }

    int j = lane & 7, grp = lane >> 3;
    int a_row = wm * 32 + ((grp & 1) << 3) + j;
    int a_ub  = grp >> 1;
    int b_row = wn * 64 + (((grp >> 1) & 1) << 3) + j;
    int b_r7  = b_row & 7;
    int b_ub  = grp & 1;

    float acc[2][8][4];

    #pragma unroll 1
    for (int gc = 0; gc < total; gc++) {
        int c = gc & 3;
        if (c == 0) {
            #pragma unroll
            for (int t = 0; t < 2; t++)
                #pragma unroll
                for (int u = 0; u < 8; u++)
                    #pragma unroll
                    for (int v = 0; v < 4; v++) acc[t][u][v] = 0.f;
        }
        if (gc + 1 < total) { CP_WAIT(1); } else { CP_WAIT(0); }
        __syncthreads();
        if (gc + 2 < total) {
            int nc = gc + 2;
            int r0n = (bid + (nc >> 2) * stride) * 128;
            cpA(sbase, nc % 3, tid, r0n, n, nc & 3, Arel, Aroot);
            CP_COMMIT();
        }
        uint32_t aB = sbase + GB_A0 + (uint32_t)(gc % 3) * 16384;
        #pragma unroll
        for (int ks = 0; ks < 4; ks++) {
            uint4 af[2];
            #pragma unroll
            for (int t = 0; t < 2; t++) {
                int row = a_row + t * 16;
                int u = ks * 2 + a_ub;
                ldsm4(af[t], aB + row * 128 + (((u ^ (row & 7)) & 7) << 4));
            }
            uint4 bf[4];
            #pragma unroll
            for (int p = 0; p < 4; p++) {
                int row = b_row + p * 16;
                int uu = c * 8 + ks * 2 + b_ub;
                int phys = (uu & 0x18) | ((uu ^ b_r7) & 7);
                ldsm4(bf[p], sbase + GB_W + row * 512 + phys * 16);
            }
            #pragma unroll
            for (int t = 0; t < 2; t++)
                #pragma unroll
                for (int u = 0; u < 8; u++) {
                    int p = u >> 1;
                    uint32_t b0 = (u & 1) ? bf[p].z : bf[p].x;
                    uint32_t b1 = (u & 1) ? bf[p].w : bf[p].y;
                    mma16816(acc[t][u], af[t], b0, b1);
                }
        }
        if (c == 3) {
            // epilogue for this tile (next tile's chunks already in flight)
            int r0 = (bid + (gc >> 2) * stride) * 128;
            const float* bias = (const float*)smem;
            int rb = r0 + wm * 32 + (lane >> 2);
            int cb = wn * 64 + ((lane & 3) << 1);
            #pragma unroll
            for (int t = 0; t < 2; t++) {
                #pragma unroll
                for (int u = 0; u < 8; u++) {
                    int cc = cb + u * 8;
                    float b0v = bias[cc], b1v = bias[cc + 1];
                    #pragma unroll
                    for (int h = 0; h < 2; h++) {
                        int r = rb + t * 16 + h * 8;
                        if (r >= n) continue;
                        float vx = acc[t][u][h * 2 + 0] + b0v;
                        float vy = acc[t][u][h * 2 + 1] + b1v;
                        if (MODE == 0) {
                            vx = (vx >= 0.f) ? vx : 0.1f * vx;
                            vy = (vy >= 0.f) ? vy : 0.1f * vy;
                            __half2* op =
                                (__half2*)((__half*)outv + (size_t)r * W + cc);
                            *op = __floats2half2_rn(vx, vy);
                        } else {
                            float2 rr =
                                *(const float2*)(resid + (size_t)r * W + cc);
                            vx += rr.x; vy += rr.y;
                            *(float2*)((float*)outv + (size_t)r * W + cc) =
                                make_float2(vx, vy);
                        }
                    }
                }
            }
        }
    }
}

// ---------------- launch -----------------------------------------------------
extern "C" void kernel_launch(void* const* d_in, const int* in_sizes, int n_in,
                              void* d_out, int out_size)
{
    const float* x      = (const float*)d_in[0];
    const int*   eidx   = (const int*)d_in[1];
    const float* ew     = (const float*)d_in[2];
    const int*   bmap   = (const int*)d_in[3];
    const float* gnw    = (const float*)d_in[4];
    const float* gnb    = (const float*)d_in[5];
    const float* msc    = (const float*)d_in[6];
    const float* Wrel1  = (const float*)d_in[7];
    const float* brel1  = (const float*)d_in[8];
    const float* Wroot1 = (const float*)d_in[9];
    const float* Wrel2  = (const float*)d_in[10];
    const float* brel2  = (const float*)d_in[11];
    const float* Wroot2 = (const float*)d_in[12];
    float* out = (float*)d_out;

    int n = in_sizes[0] / W;
    int E = in_sizes[2];
    const int* src = eidx;
    const int* dst = eidx + E;

    void *p_xnh, *p_aggh, *p_h1h, *p_wh;
    cudaGetSymbolAddress(&p_xnh, g_xnh);
    cudaGetSymbolAddress(&p_aggh, g_aggh);
    cudaGetSymbolAddress(&p_h1h, g_h1h);
    cudaGetSymbolAddress(&p_wh, g_wh);
    __half* xnh  = (__half*)p_xnh;
    __half* aggh = (__half*)p_aggh;
    __half* h1h  = (__half*)p_h1h;
    __half* wh   = (__half*)p_wh;

    cudaFuncSetAttribute(gemm_h_kernel<0>,
                         cudaFuncAttributeMaxDynamicSharedMemorySize, GB_SMEM);
    cudaFuncSetAttribute(gemm_h_kernel<1>,
                         cudaFuncAttributeMaxDynamicSharedMemorySize, GB_SMEM);

    // K1: stats || hist || wprep
    int nbS = (n + 255) / 256;
    int nbH = (E + 1023) / 1024;
    int nbW = 128;
    k1_kernel<<<nbS + nbH + nbW, 256>>>(x, bmap, n, dst, E,
                                        Wrel1, Wroot1, Wrel2, Wroot2, nbS, nbH);

    // K2: finalize || scan1
    int n4 = (n + 3) / 4;
    int nscan = (n4 + 1023) / 1024;
    int nbF = (G * W) / 256;
    k2_kernel<<<nbF + nscan, 256>>>(gnw, gnb, msc, n4, nbF);

    // K3: scan3 (inline scan2)
    k3_kernel<<<nscan, 256>>>(n4, nscan, n);

    // K4: place || norm
    int nbP = (E + 1023) / 1024;
    int total4 = n * 32;
    int nbN = (total4 + 255) / 256;
    k4_kernel<<<nbP + nbN, 256>>>(src, dst, ew, E,
                                  (const float4*)x, bmap, total4, nbP);

    // conv1: gather + persistent GEMM(+LeakyReLU) -> fp16 h1
    int gwBlocks = (n * 32 + 255) / 256;
    gather_kernel<<<gwBlocks, 256>>>((const uint2*)xnh, (uint2*)aggh, n);
    int nTiles = (n + 127) / 128;
    int gGrid = nTiles < 148 ? nTiles : 148;
    gemm_h_kernel<0><<<gGrid, 256, GB_SMEM>>>(
        aggh, xnh, wh, brel1, nullptr, h1h, n, nTiles);

    // conv2: gather + persistent GEMM(+residual) -> fp32 out
    gather_kernel<<<gwBlocks, 256>>>((const uint2*)h1h, (uint2*)aggh, n);
    gemm_h_kernel<1><<<gGrid, 256, GB_SMEM>>>(
        aggh, h1h, wh + 128 * 256, brel2, x, out, n, nTiles);
}

// round 12
// speedup vs baseline: 1.0877x; 1.0877x over previous
#include <cuda_runtime.h>
#include <cuda_fp16.h>
#include <cstdint>

#define W 128
#define G 64
#define MAXN 100000
#define MAXE 625000
#define EPS 1e-5f

// ---------------- scratch (static device globals; zero-initialized) ----------
__device__ __half g_xnh[MAXN * W];
__device__ __half g_aggh[MAXN * W];
__device__ __half g_h1h[MAXN * W];
__device__ __half g_wh[2 * 128 * 256];
__device__ float g_sum[G * W];        // self-cleaned by finalize
__device__ float g_sumsq[G * W];      // self-cleaned by finalize
__device__ float g_cnt[G];            // self-cleaned by finalize
__device__ float g_alpha[G * W];
__device__ float g_beta[G * W];
__device__ int   g_deg[MAXN];         // self-cleaned by scan3
__device__ int   g_base[MAXN + 4];
__device__ int   g_cur[MAXN];         // self-cleaned by gather
__device__ int2  g_elist[MAXE];
__device__ int   g_bsum[64];

// ---------------- PTX helpers (sm_80/90 baseline only) -----------------------
__device__ __forceinline__ uint32_t smem_u32(const void* p) {
    uint32_t a;
    asm("{ .reg .u64 t; cvta.to.shared.u64 t, %1; cvt.u32.u64 %0, t; }"
        : "=r"(a) : "l"(p));
    return a;
}
__device__ __forceinline__ void ldsm4(uint4& r, uint32_t addr) {
    asm volatile("ldmatrix.sync.aligned.m8n8.x4.shared.b16 {%0,%1,%2,%3}, [%4];"
                 : "=r"(r.x), "=r"(r.y), "=r"(r.z), "=r"(r.w) : "r"(addr));
}
__device__ __forceinline__ void mma16816(float* d, const uint4& a,
                                         uint32_t b0, uint32_t b1) {
    asm volatile(
        "mma.sync.aligned.m16n8k16.row.col.f32.f16.f16.f32 "
        "{%0,%1,%2,%3}, {%4,%5,%6,%7}, {%8,%9}, {%0,%1,%2,%3};"
        : "+f"(d[0]), "+f"(d[1]), "+f"(d[2]), "+f"(d[3])
        : "r"(a.x), "r"(a.y), "r"(a.z), "r"(a.w), "r"(b0), "r"(b1));
}
__device__ __forceinline__ void cp16(uint32_t dst, const void* src, bool pred) {
    int sz = pred ? 16 : 0;
    asm volatile("cp.async.cg.shared.global [%0], [%1], 16, %2;"
                 :: "r"(dst), "l"(src), "r"(sz) : "memory");
}
#define CP_COMMIT() asm volatile("cp.async.commit_group;" ::: "memory")
#define CP_WAIT(N)  asm volatile("cp.async.wait_group %0;" :: "n"(N) : "memory")

// ================= K1: stats || hist || wprep (grid-partitioned) =============
__global__ __launch_bounds__(256) void k1_kernel(
    const float* __restrict__ x, const int* __restrict__ bmap, int n,
    const int* __restrict__ dst, int E,
    const float* __restrict__ Wr1, const float* __restrict__ Wo1,
    const float* __restrict__ Wr2, const float* __restrict__ Wo2,
    int nbS, int nbH)
{
    int b = blockIdx.x, tid = threadIdx.x;
    if (b < nbS) {
        int f = tid & 127, sub = tid >> 7;
        int n0 = b * 256 + sub * 128;
        if (n0 >= n) return;
        int n1 = min(n0 + 128, n);
        float s = 0.f, ss = 0.f;
        int curg = __ldg(bmap + n0);
        #pragma unroll 1
        for (int r = n0; r < n1; r++) {
            int g = __ldg(bmap + r);
            if (g != curg) {
                atomicAdd(&g_sum[curg * W + f], s);
                atomicAdd(&g_sumsq[curg * W + f], ss);
                s = 0.f; ss = 0.f; curg = g;
            }
            float v = x[(size_t)r * W + f];
            s += v; ss += v * v;
        }
        atomicAdd(&g_sum[curg * W + f], s);
        atomicAdd(&g_sumsq[curg * W + f], ss);
        if (f == 0) {
            int cg = __ldg(bmap + n0), rs = n0;
            for (int r = n0; r < n1; r++) {
                int g = __ldg(bmap + r);
                if (g != cg) {
                    atomicAdd(&g_cnt[cg], (float)(r - rs));
                    cg = g; rs = r;
                }
            }
            atomicAdd(&g_cnt[cg], (float)(n1 - rs));
        }
    } else if (b < nbS + nbH) {
        int i4 = (b - nbS) * 256 + tid;
        int e = i4 * 4;
        if (e + 3 < E) {
            int4 d = __ldg((const int4*)dst + i4);
            atomicAdd(&g_deg[d.x], 1);
            atomicAdd(&g_deg[d.y], 1);
            atomicAdd(&g_deg[d.z], 1);
            atomicAdd(&g_deg[d.w], 1);
        } else {
            for (int j2 = 0; j2 < 4; j2++)
                if (e + j2 < E) atomicAdd(&g_deg[__ldg(dst + e + j2)], 1);
        }
    } else {
        int idx = (b - nbS - nbH) * 256 + tid;
        int conv = idx >> 14;
        int rem  = idx & 16383;
        int row  = rem >> 7;
        int c2   = rem & 127;
        const float* Wr = conv ? Wr2 : Wr1;
        const float* Wo = conv ? Wo2 : Wo1;
        const float* s = (c2 < 64) ? (Wr + row * 128 + c2 * 2)
                                   : (Wo + row * 128 + (c2 - 64) * 2);
        float2 v = *(const float2*)s;
        ((__half2*)(g_wh + (size_t)conv * 128 * 256 + row * 256))[c2] =
            __floats2half2_rn(v.x, v.y);
    }
}

// ================= K2: finalize || scan1 =====================================
__global__ __launch_bounds__(256) void k2_kernel(
    const float* __restrict__ gnw, const float* __restrict__ gnb,
    const float* __restrict__ msc, int n4, int nbF)
{
    int b = blockIdx.x, tid = threadIdx.x, lane = tid & 31, wid = tid >> 5;
    if (b < nbF) {
        int idx = b * 256 + tid;
        int g = idx >> 7, f = idx & 127;
        float cnt  = g_cnt[g];
        float inv  = (cnt > 0.f) ? (1.f / cnt) : 0.f;
        float mean = g_sum[idx] * inv;
        float q    = g_sumsq[idx] * inv;
        g_sum[idx] = 0.f;
        g_sumsq[idx] = 0.f;
        float m    = __ldg(msc + f);
        float var  = q - mean * mean * m * (2.f - m);
        float istd = rsqrtf(var + EPS);
        float a    = __ldg(gnw + f) * istd;
        g_alpha[idx] = a;
        g_beta[idx]  = __ldg(gnb + f) - a * m * mean;
        __syncthreads();
        if (f == 0) g_cnt[g] = 0.f;
    } else {
        __shared__ int wS[8];
        int sb = b - nbF;
        const int4* dp = (const int4*)g_deg;
        int i4 = sb * 1024 + tid * 4;
        int s = 0;
        #pragma unroll
        for (int j2 = 0; j2 < 4; j2++) {
            if (i4 + j2 < n4) {
                int4 v = dp[i4 + j2];
                s += v.x + v.y + v.z + v.w;
            }
        }
        #pragma unroll
        for (int o = 16; o > 0; o >>= 1) s += __shfl_down_sync(~0u, s, o);
        if (lane == 0) wS[wid] = s;
        __syncthreads();
        if (tid == 0) {
            int t = 0;
            #pragma unroll
            for (int k = 0; k < 8; k++) t += wS[k];
            g_bsum[sb] = t;
        }
    }
}

// ================= K3: scan3 (with inline scan2 over g_bsum) =================
__global__ __launch_bounds__(256) void k3_kernel(int n4, int nscan, int n)
{
    __shared__ int wS[8];
    __shared__ int boff;
    int b = blockIdx.x, tid = threadIdx.x, lane = tid & 31, wid = tid >> 5;
    if (tid == 0) {
        int run = 0;
        for (int i = 0; i < b; i++) run += g_bsum[i];
        boff = run;
        if (b == 0) {
            int tot = 0;
            for (int i = 0; i < nscan; i++) tot += g_bsum[i];
            g_base[n] = tot;
        }
    }
    int4* dp = (int4*)g_deg;
    int i4 = b * 1024 + tid * 4;
    int4 v[4];
    int s = 0;
    #pragma unroll
    for (int j2 = 0; j2 < 4; j2++) {
        v[j2] = make_int4(0, 0, 0, 0);
        if (i4 + j2 < n4) {
            v[j2] = dp[i4 + j2];
            dp[i4 + j2] = make_int4(0, 0, 0, 0);
        }
        s += v[j2].x + v[j2].y + v[j2].z + v[j2].w;
    }
    int x = s;
    #pragma unroll
    for (int o = 1; o < 32; o <<= 1) {
        int y = __shfl_up_sync(~0u, x, o);
        if (lane >= o) x += y;
    }
    if (lane == 31) wS[wid] = x;
    __syncthreads();
    int woff = 0;
    #pragma unroll
    for (int k = 0; k < 8; k++)
        if (k < wid) woff += wS[k];
    int run = boff + woff + x - s;
    int4* bp = (int4*)g_base;
    #pragma unroll
    for (int j2 = 0; j2 < 4; j2++) {
        if (i4 + j2 < n4) {
            int4 o;
            o.x = run; run += v[j2].x;
            o.y = run; run += v[j2].y;
            o.z = run; run += v[j2].z;
            o.w = run; run += v[j2].w;
            bp[i4 + j2] = o;
        }
    }
}

// ================= K4: place || norm =========================================
__global__ __launch_bounds__(256) void k4_kernel(
    const int* __restrict__ src, const int* __restrict__ dst,
    const float* __restrict__ ew, int E,
    const float4* __restrict__ x, const int* __restrict__ bmap, int total4,
    int nbP)
{
    int b = blockIdx.x, tid = threadIdx.x;
    if (b < nbP) {
        int i4 = b * 256 + tid;
        int e = i4 * 4;
        if (e + 3 < E) {
            int4 sv = __ldg((const int4*)src + i4);
            int4 dv = __ldg((const int4*)dst + i4);
            float4 wv = __ldg((const float4*)ew + i4);
            int p;
            p = g_base[dv.x] + atomicAdd(&g_cur[dv.x], 1);
            g_elist[p] = make_int2(sv.x, __float_as_int(wv.x));
            p = g_base[dv.y] + atomicAdd(&g_cur[dv.y], 1);
            g_elist[p] = make_int2(sv.y, __float_as_int(wv.y));
            p = g_base[dv.z] + atomicAdd(&g_cur[dv.z], 1);
            g_elist[p] = make_int2(sv.z, __float_as_int(wv.z));
            p = g_base[dv.w] + atomicAdd(&g_cur[dv.w], 1);
            g_elist[p] = make_int2(sv.w, __float_as_int(wv.w));
        } else {
            for (int j2 = 0; j2 < 4; j2++) {
                int ee = e + j2;
                if (ee < E) {
                    int d = __ldg(dst + ee);
                    int p = g_base[d] + atomicAdd(&g_cur[d], 1);
                    g_elist[p] = make_int2(__ldg(src + ee),
                                           __float_as_int(__ldg(ew + ee)));
                }
            }
        }
    } else {
        int idx = (b - nbP) * 256 + tid;
        if (idx >= total4) return;
        int r = idx >> 5, c = idx & 31;
        int g = __ldg(bmap + r);
        float4 xv = __ldg(x + idx);
        float4 a = ((const float4*)g_alpha)[g * 32 + c];
        float4 bb = ((const float4*)g_beta)[g * 32 + c];
        float ox = fmaf(a.x, xv.x, bb.x);
        float oy = fmaf(a.y, xv.y, bb.y);
        float oz = fmaf(a.z, xv.z, bb.z);
        float ow = fmaf(a.w, xv.w, bb.w);
        uint2 o;
        *(__half2*)&o.x = __floats2half2_rn(ox, oy);
        *(__half2*)&o.y = __floats2half2_rn(oz, ow);
        ((uint2*)g_xnh)[idx] = o;
    }
}

// ---------------- gather (fp16 rows, fp32 accumulate, 4-edge ILP) ------------
__global__ __launch_bounds__(256) void gather_kernel(
    const uint2* __restrict__ in, uint2* __restrict__ agg, int n)
{
    int warp = (blockIdx.x * 256 + threadIdx.x) >> 5;
    if (warp >= n) return;
    int c = threadIdx.x & 31;
    int b0 = g_base[warp], b1 = g_base[warp + 1];
    if (c == 0) g_cur[warp] = 0;
    float4 acc = make_float4(0.f, 0.f, 0.f, 0.f);
    int e = b0;
    #pragma unroll 1
    for (; e + 4 <= b1; e += 4) {
        int2 s0 = __ldg(&g_elist[e]);
        int2 s1 = __ldg(&g_elist[e + 1]);
        int2 s2 = __ldg(&g_elist[e + 2]);
        int2 s3 = __ldg(&g_elist[e + 3]);
        uint2 v0 = __ldg(in + (size_t)s0.x * 32 + c);
        uint2 v1 = __ldg(in + (size_t)s1.x * 32 + c);
        uint2 v2 = __ldg(in + (size_t)s2.x * 32 + c);
        uint2 v3 = __ldg(in + (size_t)s3.x * 32 + c);
        float w0 = __int_as_float(s0.y), w1 = __int_as_float(s1.y);
        float w2 = __int_as_float(s2.y), w3 = __int_as_float(s3.y);
        float2 a0 = __half22float2(*(__half2*)&v0.x);
        float2 a1 = __half22float2(*(__half2*)&v0.y);
        acc.x = fmaf(w0, a0.x, acc.x); acc.y = fmaf(w0, a0.y, acc.y);
        acc.z = fmaf(w0, a1.x, acc.z); acc.w = fmaf(w0, a1.y, acc.w);
        float2 c0 = __half22float2(*(__half2*)&v1.x);
        float2 c1 = __half22float2(*(__half2*)&v1.y);
        acc.x = fmaf(w1, c0.x, acc.x); acc.y = fmaf(w1, c0.y, acc.y);
        acc.z = fmaf(w1, c1.x, acc.z); acc.w = fmaf(w1, c1.y, acc.w);
        float2 d0 = __half22float2(*(__half2*)&v2.x);
        float2 d1 = __half22float2(*(__half2*)&v2.y);
        acc.x = fmaf(w2, d0.x, acc.x); acc.y = fmaf(w2, d0.y, acc.y);
        acc.z = fmaf(w2, d1.x, acc.z); acc.w = fmaf(w2, d1.y, acc.w);
        float2 e0 = __half22float2(*(__half2*)&v3.x);
        float2 e1 = __half22float2(*(__half2*)&v3.y);
        acc.x = fmaf(w3, e0.x, acc.x); acc.y = fmaf(w3, e0.y, acc.y);
        acc.z = fmaf(w3, e1.x, acc.z); acc.w = fmaf(w3, e1.y, acc.w);
    }
    #pragma unroll 1
    for (; e + 2 <= b1; e += 2) {
        int2 s0 = __ldg(&g_elist[e]);
        int2 s1 = __ldg(&g_elist[e + 1]);
        uint2 v0 = __ldg(in + (size_t)s0.x * 32 + c);
        uint2 v1 = __ldg(in + (size_t)s1.x * 32 + c);
        float w0 = __int_as_float(s0.y), w1 = __int_as_float(s1.y);
        float2 a0 = __half22float2(*(__half2*)&v0.x);
        float2 a1 = __half22float2(*(__half2*)&v0.y);
        acc.x = fmaf(w0, a0.x, acc.x); acc.y = fmaf(w0, a0.y, acc.y);
        acc.z = fmaf(w0, a1.x, acc.z); acc.w = fmaf(w0, a1.y, acc.w);
        float2 b0f = __half22float2(*(__half2*)&v1.x);
        float2 b1f = __half22float2(*(__half2*)&v1.y);
        acc.x = fmaf(w1, b0f.x, acc.x); acc.y = fmaf(w1, b0f.y, acc.y);
        acc.z = fmaf(w1, b1f.x, acc.z); acc.w = fmaf(w1, b1f.y, acc.w);
    }
    if (e < b1) {
        int2 s0 = __ldg(&g_elist[e]);
        uint2 v0 = __ldg(in + (size_t)s0.x * 32 + c);
        float w0 = __int_as_float(s0.y);
        float2 a0 = __half22float2(*(__half2*)&v0.x);
        float2 a1 = __half22float2(*(__half2*)&v0.y);
        acc.x = fmaf(w0, a0.x, acc.x); acc.y = fmaf(w0, a0.y, acc.y);
        acc.z = fmaf(w0, a1.x, acc.z); acc.w = fmaf(w0, a1.y, acc.w);
    }
    uint2 o;
    *(__half2*)&o.x = __floats2half2_rn(acc.x, acc.y);
    *(__half2*)&o.y = __floats2half2_rn(acc.z, acc.w);
    agg[(size_t)warp * 32 + c] = o;
}

// ---------------- fp16 warp-MMA GEMM, cp.async pipelined (round-9 config) ----
#define GB_A0   1024
#define GB_W    (GB_A0 + 3 * 16384)
#define GB_SMEM (GB_W + 65536)

__device__ __forceinline__ void cpA(uint32_t sbase, int buf, int tid, int r0,
                                    int n, int c,
                                    const __half* __restrict__ Arel,
                                    const __half* __restrict__ Aroot)
{
    const char* As = (const char*)((c < 2) ? Arel : Aroot);
    int off = (c & 1) * 128;
    #pragma unroll
    for (int i = 0; i < 4; i++) {
        int q = tid + i * 256;
        int row = q >> 3, u = q & 7;
        int gr = r0 + row;
        cp16(sbase + GB_A0 + buf * 16384 + row * 128 + (((u ^ (row & 7)) & 7) << 4),
             As + (size_t)gr * 256 + off + u * 16, gr < n);
    }
}

template <int MODE>
__global__ __launch_bounds__(256) void gemm_h_kernel(
    const __half* __restrict__ Arel, const __half* __restrict__ Aroot,
    const __half* __restrict__ wh, const float* __restrict__ brel,
    const float* __restrict__ resid, void* __restrict__ outv, int n)
{
    extern __shared__ char smem[];
    uint32_t sbase = smem_u32(smem);
    int tid = threadIdx.x, wid = tid >> 5, lane = tid & 31;
    int wm = wid & 3, wn = wid >> 2;
    int r0 = blockIdx.x * 128;

    if (tid < 128) ((float*)smem)[tid] = __ldg(brel + tid);

    #pragma unroll
    for (int i = 0; i < 16; i++) {
        int q = tid + i * 256;
        int row = q >> 5, uu = q & 31;
        int phys = (uu & 0x18) | ((uu ^ row) & 7);
        cp16(sbase + GB_W + row * 512 + phys * 16,
             (const char*)wh + (size_t)row * 512 + uu * 16, true);
    }
    cpA(sbase, 0, tid, r0, n, 0, Arel, Aroot);
    CP_COMMIT();
    cpA(sbase, 1, tid, r0, n, 1, Arel, Aroot);
    CP_COMMIT();

    float acc[2][8][4];
    #pragma unroll
    for (int t = 0; t < 2; t++)
        #pragma unroll
        for (int u = 0; u < 8; u++)
            #pragma unroll
            for (int v = 0; v < 4; v++) acc[t][u][v] = 0.f;

    int j = lane & 7, grp = lane >> 3;
    int a_row = wm * 32 + ((grp & 1) << 3) + j;
    int a_ub  = grp >> 1;
    int b_row = wn * 64 + (((grp >> 1) & 1) << 3) + j;
    int b_r7  = b_row & 7;
    int b_ub  = grp & 1;

    #pragma unroll 1
    for (int c = 0; c < 4; c++) {
        if (c < 3) { CP_WAIT(1); } else { CP_WAIT(0); }
        __syncthreads();
        if (c < 2) {
            cpA(sbase, (c + 2) % 3, tid, r0, n, c + 2, Arel, Aroot);
            CP_COMMIT();
        }
        uint32_t aB = sbase + GB_A0 + (uint32_t)(c % 3) * 16384;
        #pragma unroll
        for (int ks = 0; ks < 4; ks++) {
            uint4 af[2];
            #pragma unroll
            for (int t = 0; t < 2; t++) {
                int row = a_row + t * 16;
                int u = ks * 2 + a_ub;
                ldsm4(af[t], aB + row * 128 + (((u ^ (row & 7)) & 7) << 4));
            }
            uint4 bf[4];
            #pragma unroll
            for (int p = 0; p < 4; p++) {
                int row = b_row + p * 16;
                int uu = c * 8 + ks * 2 + b_ub;
                int phys = (uu & 0x18) | ((uu ^ b_r7) & 7);
                ldsm4(bf[p], sbase + GB_W + row * 512 + phys * 16);
            }
            #pragma unroll
            for (int t = 0; t < 2; t++)
                #pragma unroll
                for (int u = 0; u < 8; u++) {
                    int p = u >> 1;
                    uint32_t b0 = (u & 1) ? bf[p].z : bf[p].x;
                    uint32_t b1 = (u & 1) ? bf[p].w : bf[p].y;
                    mma16816(acc[t][u], af[t], b0, b1);
                }
        }
    }

    const float* bias = (const float*)smem;
    int rb = r0 + wm * 32 + (lane >> 2);
    int cb = wn * 64 + ((lane & 3) << 1);
    #pragma unroll
    for (int t = 0; t < 2; t++) {
        #pragma unroll
        for (int u = 0; u < 8; u++) {
            int cc = cb + u * 8;
            float b0v = bias[cc], b1v = bias[cc + 1];
            #pragma unroll
            for (int h = 0; h < 2; h++) {
                int r = rb + t * 16 + h * 8;
                if (r >= n) continue;
                float vx = acc[t][u][h * 2 + 0] + b0v;
                float vy = acc[t][u][h * 2 + 1] + b1v;
                if (MODE == 0) {
                    vx = (vx >= 0.f) ? vx : 0.1f * vx;
                    vy = (vy >= 0.f) ? vy : 0.1f * vy;
                    __half2* op = (__half2*)((__half*)outv + (size_t)r * W + cc);
                    *op = __floats2half2_rn(vx, vy);
                } else {
                    float2 rr = *(const float2*)(resid + (size_t)r * W + cc);
                    vx += rr.x; vy += rr.y;
                    *(float2*)((float*)outv + (size_t)r * W + cc) =
                        make_float2(vx, vy);
                }
            }
        }
    }
}

// ---------------- launch -----------------------------------------------------
extern "C" void kernel_launch(void* const* d_in, const int* in_sizes, int n_in,
                              void* d_out, int out_size)
{
    const float* x      = (const float*)d_in[0];
    const int*   eidx   = (const int*)d_in[1];
    const float* ew     = (const float*)d_in[2];
    const int*   bmap   = (const int*)d_in[3];
    const float* gnw    = (const float*)d_in[4];
    const float* gnb    = (const float*)d_in[5];
    const float* msc    = (const float*)d_in[6];
    const float* Wrel1  = (const float*)d_in[7];
    const float* brel1  = (const float*)d_in[8];
    const float* Wroot1 = (const float*)d_in[9];
    const float* Wrel2  = (const float*)d_in[10];
    const float* brel2  = (const float*)d_in[11];
    const float* Wroot2 = (const float*)d_in[12];
    float* out = (float*)d_out;

    int n = in_sizes[0] / W;
    int E = in_sizes[2];
    const int* src = eidx;
    const int* dst = eidx + E;

    void *p_xnh, *p_aggh, *p_h1h, *p_wh;
    cudaGetSymbolAddress(&p_xnh, g_xnh);
    cudaGetSymbolAddress(&p_aggh, g_aggh);
    cudaGetSymbolAddress(&p_h1h, g_h1h);
    cudaGetSymbolAddress(&p_wh, g_wh);
    __half* xnh  = (__half*)p_xnh;
    __half* aggh = (__half*)p_aggh;
    __half* h1h  = (__half*)p_h1h;
    __half* wh   = (__half*)p_wh;

    cudaFuncSetAttribute(gemm_h_kernel<0>,
                         cudaFuncAttributeMaxDynamicSharedMemorySize, GB_SMEM);
    cudaFuncSetAttribute(gemm_h_kernel<1>,
                         cudaFuncAttributeMaxDynamicSharedMemorySize, GB_SMEM);

    // K1: stats || hist || wprep
    int nbS = (n + 255) / 256;
    int nbH = (E + 1023) / 1024;
    int nbW = 128;
    k1_kernel<<<nbS + nbH + nbW, 256>>>(x, bmap, n, dst, E,
                                        Wrel1, Wroot1, Wrel2, Wroot2, nbS, nbH);

    // K2: finalize || scan1
    int n4 = (n + 3) / 4;
    int nscan = (n4 + 1023) / 1024;
    int nbF = (G * W) / 256;
    k2_kernel<<<nbF + nscan, 256>>>(gnw, gnb, msc, n4, nbF);

    // K3: scan3 (inline scan2)
    k3_kernel<<<nscan, 256>>>(n4, nscan, n);

    // K4: place || norm
    int nbP = (E + 1023) / 1024;
    int total4 = n * 32;
    int nbN = (total4 + 255) / 256;
    k4_kernel<<<nbP + nbN, 256>>>(src, dst, ew, E,
                                  (const float4*)x, bmap, total4, nbP);

    // conv1: gather + GEMM(+LeakyReLU) -> fp16 h1
    int gwBlocks = (n * 32 + 255) / 256;
    gather_kernel<<<gwBlocks, 256>>>((const uint2*)xnh, (uint2*)aggh, n);
    int gBlocks = (n + 127) / 128;
    gemm_h_kernel<0><<<gBlocks, 256, GB_SMEM>>>(
        aggh, xnh, wh, brel1, nullptr, h1h, n);

    // conv2: gather + GEMM(+residual) -> fp32 out
    gather_kernel<<<gwBlocks, 256>>>((const uint2*)h1h, (uint2*)aggh, n);
    gemm_h_kernel<1><<<gBlocks, 256, GB_SMEM>>>(
        aggh, h1h, wh + 128 * 256, brel2, x, out, n);
}

// round 13
// speedup vs baseline: 1.0995x; 1.0108x over previous
#include <cuda_runtime.h>
#include <cuda_fp16.h>
#include <cstdint>

#define W 128
#define G 64
#define MAXN 100000
#define MAXE 625000
#define EPS 1e-5f

// ---------------- scratch (static device globals; zero-initialized) ----------
__device__ __half g_xnh[MAXN * W];
__device__ __half g_aggh[MAXN * W];
__device__ __half g_h1h[MAXN * W];
__device__ __half g_wh[2 * 128 * 256];
__device__ float g_sum[G * W];        // self-cleaned by finalize
__device__ float g_sumsq[G * W];      // self-cleaned by finalize
__device__ float g_cnt[G];            // self-cleaned by finalize
__device__ float g_alpha[G * W];
__device__ float g_beta[G * W];
__device__ int   g_deg[MAXN];         // self-cleaned by scan3
__device__ int   g_base[MAXN + 4];
__device__ int   g_cur[MAXN];         // self-cleaned by gather
__device__ int2  g_elist[MAXE];
__device__ int   g_bsum[64];

// ---------------- PTX helpers (sm_80/90 baseline only) -----------------------
__device__ __forceinline__ uint32_t smem_u32(const void* p) {
    uint32_t a;
    asm("{ .reg .u64 t; cvta.to.shared.u64 t, %1; cvt.u32.u64 %0, t; }"
        : "=r"(a) : "l"(p));
    return a;
}
__device__ __forceinline__ void ldsm4(uint4& r, uint32_t addr) {
    asm volatile("ldmatrix.sync.aligned.m8n8.x4.shared.b16 {%0,%1,%2,%3}, [%4];"
                 : "=r"(r.x), "=r"(r.y), "=r"(r.z), "=r"(r.w) : "r"(addr));
}
__device__ __forceinline__ void mma16816(float* d, const uint4& a,
                                         uint32_t b0, uint32_t b1) {
    asm volatile(
        "mma.sync.aligned.m16n8k16.row.col.f32.f16.f16.f32 "
        "{%0,%1,%2,%3}, {%4,%5,%6,%7}, {%8,%9}, {%0,%1,%2,%3};"
        : "+f"(d[0]), "+f"(d[1]), "+f"(d[2]), "+f"(d[3])
        : "r"(a.x), "r"(a.y), "r"(a.z), "r"(a.w), "r"(b0), "r"(b1));
}
__device__ __forceinline__ void cp16(uint32_t dst, const void* src, bool pred) {
    int sz = pred ? 16 : 0;
    asm volatile("cp.async.cg.shared.global [%0], [%1], 16, %2;"
                 :: "r"(dst), "l"(src), "r"(sz) : "memory");
}
#define CP_COMMIT() asm volatile("cp.async.commit_group;" ::: "memory")
#define CP_WAIT(N)  asm volatile("cp.async.wait_group %0;" :: "n"(N) : "memory")

// ================= K1: stats || hist || wprep (grid-partitioned) =============
__global__ __launch_bounds__(256) void k1_kernel(
    const float* __restrict__ x, const int* __restrict__ bmap, int n,
    const int* __restrict__ dst, int E,
    const float* __restrict__ Wr1, const float* __restrict__ Wo1,
    const float* __restrict__ Wr2, const float* __restrict__ Wo2,
    int nbS, int nbH)
{
    int b = blockIdx.x, tid = threadIdx.x;
    if (b < nbS) {
        int f = tid & 127, sub = tid >> 7;
        int n0 = b * 256 + sub * 128;
        if (n0 >= n) return;
        int n1 = min(n0 + 128, n);
        float s = 0.f, ss = 0.f;
        int curg = __ldg(bmap + n0);
        #pragma unroll 1
        for (int r = n0; r < n1; r++) {
            int g = __ldg(bmap + r);
            if (g != curg) {
                atomicAdd(&g_sum[curg * W + f], s);
                atomicAdd(&g_sumsq[curg * W + f], ss);
                s = 0.f; ss = 0.f; curg = g;
            }
            float v = x[(size_t)r * W + f];
            s += v; ss += v * v;
        }
        atomicAdd(&g_sum[curg * W + f], s);
        atomicAdd(&g_sumsq[curg * W + f], ss);
        if (f == 0) {
            int cg = __ldg(bmap + n0), rs = n0;
            for (int r = n0; r < n1; r++) {
                int g = __ldg(bmap + r);
                if (g != cg) {
                    atomicAdd(&g_cnt[cg], (float)(r - rs));
                    cg = g; rs = r;
                }
            }
            atomicAdd(&g_cnt[cg], (float)(n1 - rs));
        }
    } else if (b < nbS + nbH) {
        int i4 = (b - nbS) * 256 + tid;
        int e = i4 * 4;
        if (e + 3 < E) {
            int4 d = __ldg((const int4*)dst + i4);
            atomicAdd(&g_deg[d.x], 1);
            atomicAdd(&g_deg[d.y], 1);
            atomicAdd(&g_deg[d.z], 1);
            atomicAdd(&g_deg[d.w], 1);
        } else {
            for (int j2 = 0; j2 < 4; j2++)
                if (e + j2 < E) atomicAdd(&g_deg[__ldg(dst + e + j2)], 1);
        }
    } else {
        int idx = (b - nbS - nbH) * 256 + tid;
        int conv = idx >> 14;
        int rem  = idx & 16383;
        int row  = rem >> 7;
        int c2   = rem & 127;
        const float* Wr = conv ? Wr2 : Wr1;
        const float* Wo = conv ? Wo2 : Wo1;
        const float* s = (c2 < 64) ? (Wr + row * 128 + c2 * 2)
                                   : (Wo + row * 128 + (c2 - 64) * 2);
        float2 v = *(const float2*)s;
        ((__half2*)(g_wh + (size_t)conv * 128 * 256 + row * 256))[c2] =
            __floats2half2_rn(v.x, v.y);
    }
}

// ================= K2: finalize || scan1 =====================================
__global__ __launch_bounds__(256) void k2_kernel(
    const float* __restrict__ gnw, const float* __restrict__ gnb,
    const float* __restrict__ msc, int n4, int nbF)
{
    int b = blockIdx.x, tid = threadIdx.x, lane = tid & 31, wid = tid >> 5;
    if (b < nbF) {
        int idx = b * 256 + tid;
        int g = idx >> 7, f = idx & 127;
        float cnt  = g_cnt[g];
        float inv  = (cnt > 0.f) ? (1.f / cnt) : 0.f;
        float mean = g_sum[idx] * inv;
        float q    = g_sumsq[idx] * inv;
        g_sum[idx] = 0.f;
        g_sumsq[idx] = 0.f;
        float m    = __ldg(msc + f);
        float var  = q - mean * mean * m * (2.f - m);
        float istd = rsqrtf(var + EPS);
        float a    = __ldg(gnw + f) * istd;
        g_alpha[idx] = a;
        g_beta[idx]  = __ldg(gnb + f) - a * m * mean;
        __syncthreads();
        if (f == 0) g_cnt[g] = 0.f;
    } else {
        __shared__ int wS[8];
        int sb = b - nbF;
        const int4* dp = (const int4*)g_deg;
        int i4 = sb * 1024 + tid * 4;
        int s = 0;
        #pragma unroll
        for (int j2 = 0; j2 < 4; j2++) {
            if (i4 + j2 < n4) {
                int4 v = dp[i4 + j2];
                s += v.x + v.y + v.z + v.w;
            }
        }
        #pragma unroll
        for (int o = 16; o > 0; o >>= 1) s += __shfl_down_sync(~0u, s, o);
        if (lane == 0) wS[wid] = s;
        __syncthreads();
        if (tid == 0) {
            int t = 0;
            #pragma unroll
            for (int k = 0; k < 8; k++) t += wS[k];
            g_bsum[sb] = t;
        }
    }
}

// ================= K3: scan3 (with inline scan2 over g_bsum) =================
__global__ __launch_bounds__(256) void k3_kernel(int n4, int nscan, int n)
{
    __shared__ int wS[8];
    __shared__ int boff;
    int b = blockIdx.x, tid = threadIdx.x, lane = tid & 31, wid = tid >> 5;
    if (tid == 0) {
        int run = 0;
        for (int i = 0; i < b; i++) run += g_bsum[i];
        boff = run;
        if (b == 0) {
            int tot = 0;
            for (int i = 0; i < nscan; i++) tot += g_bsum[i];
            g_base[n] = tot;
        }
    }
    int4* dp = (int4*)g_deg;
    int i4 = b * 1024 + tid * 4;
    int4 v[4];
    int s = 0;
    #pragma unroll
    for (int j2 = 0; j2 < 4; j2++) {
        v[j2] = make_int4(0, 0, 0, 0);
        if (i4 + j2 < n4) {
            v[j2] = dp[i4 + j2];
            dp[i4 + j2] = make_int4(0, 0, 0, 0);
        }
        s += v[j2].x + v[j2].y + v[j2].z + v[j2].w;
    }
    int x = s;
    #pragma unroll
    for (int o = 1; o < 32; o <<= 1) {
        int y = __shfl_up_sync(~0u, x, o);
        if (lane >= o) x += y;
    }
    if (lane == 31) wS[wid] = x;
    __syncthreads();
    int woff = 0;
    #pragma unroll
    for (int k = 0; k < 8; k++)
        if (k < wid) woff += wS[k];
    int run = boff + woff + x - s;
    int4* bp = (int4*)g_base;
    #pragma unroll
    for (int j2 = 0; j2 < 4; j2++) {
        if (i4 + j2 < n4) {
            int4 o;
            o.x = run; run += v[j2].x;
            o.y = run; run += v[j2].y;
            o.z = run; run += v[j2].z;
            o.w = run; run += v[j2].w;
            bp[i4 + j2] = o;
        }
    }
}

// ================= K4: place || norm =========================================
__global__ __launch_bounds__(256) void k4_kernel(
    const int* __restrict__ src, const int* __restrict__ dst,
    const float* __restrict__ ew, int E,
    const float4* __restrict__ x, const int* __restrict__ bmap, int total4,
    int nbP)
{
    int b = blockIdx.x, tid = threadIdx.x;
    if (b < nbP) {
        int i4 = b * 256 + tid;
        int e = i4 * 4;
        if (e + 3 < E) {
            int4 sv = __ldg((const int4*)src + i4);
            int4 dv = __ldg((const int4*)dst + i4);
            float4 wv = __ldg((const float4*)ew + i4);
            int p;
            p = g_base[dv.x] + atomicAdd(&g_cur[dv.x], 1);
            g_elist[p] = make_int2(sv.x, __float_as_int(wv.x));
            p = g_base[dv.y] + atomicAdd(&g_cur[dv.y], 1);
            g_elist[p] = make_int2(sv.y, __float_as_int(wv.y));
            p = g_base[dv.z] + atomicAdd(&g_cur[dv.z], 1);
            g_elist[p] = make_int2(sv.z, __float_as_int(wv.z));
            p = g_base[dv.w] + atomicAdd(&g_cur[dv.w], 1);
            g_elist[p] = make_int2(sv.w, __float_as_int(wv.w));
        } else {
            for (int j2 = 0; j2 < 4; j2++) {
                int ee = e + j2;
                if (ee < E) {
                    int d = __ldg(dst + ee);
                    int p = g_base[d] + atomicAdd(&g_cur[d], 1);
                    g_elist[p] = make_int2(__ldg(src + ee),
                                           __float_as_int(__ldg(ew + ee)));
                }
            }
        }
    } else {
        int idx = (b - nbP) * 256 + tid;
        if (idx >= total4) return;
        int r = idx >> 5, c = idx & 31;
        int g = __ldg(bmap + r);
        float4 xv = __ldg(x + idx);
        float4 a = ((const float4*)g_alpha)[g * 32 + c];
        float4 bb = ((const float4*)g_beta)[g * 32 + c];
        float ox = fmaf(a.x, xv.x, bb.x);
        float oy = fmaf(a.y, xv.y, bb.y);
        float oz = fmaf(a.z, xv.z, bb.z);
        float ow = fmaf(a.w, xv.w, bb.w);
        uint2 o;
        *(__half2*)&o.x = __floats2half2_rn(ox, oy);
        *(__half2*)&o.y = __floats2half2_rn(oz, ow);
        ((uint2*)g_xnh)[idx] = o;
    }
}

// ---------------- gather: half-warp per row, uint4 loads, 4-edge ILP ---------
__device__ __forceinline__ void gacc(float* acc, uint4 v, float w) {
    float2 p0 = __half22float2(*(__half2*)&v.x);
    float2 p1 = __half22float2(*(__half2*)&v.y);
    float2 p2 = __half22float2(*(__half2*)&v.z);
    float2 p3 = __half22float2(*(__half2*)&v.w);
    acc[0] = fmaf(w, p0.x, acc[0]); acc[1] = fmaf(w, p0.y, acc[1]);
    acc[2] = fmaf(w, p1.x, acc[2]); acc[3] = fmaf(w, p1.y, acc[3]);
    acc[4] = fmaf(w, p2.x, acc[4]); acc[5] = fmaf(w, p2.y, acc[5]);
    acc[6] = fmaf(w, p3.x, acc[6]); acc[7] = fmaf(w, p3.y, acc[7]);
}

__global__ __launch_bounds__(256) void gather_kernel(
    const uint4* __restrict__ in, uint4* __restrict__ agg, int n)
{
    int row = (blockIdx.x * 256 + threadIdx.x) >> 4;   // one half-warp per row
    if (row >= n) return;
    int c = threadIdx.x & 15;
    int b0 = g_base[row], b1 = g_base[row + 1];
    if (c == 0) g_cur[row] = 0;                        // self-clean for replay
    float acc[8];
    #pragma unroll
    for (int i = 0; i < 8; i++) acc[i] = 0.f;
    int e = b0;
    #pragma unroll 1
    for (; e + 4 <= b1; e += 4) {
        int2 s0 = __ldg(&g_elist[e]);
        int2 s1 = __ldg(&g_elist[e + 1]);
        int2 s2 = __ldg(&g_elist[e + 2]);
        int2 s3 = __ldg(&g_elist[e + 3]);
        uint4 v0 = __ldg(in + (size_t)s0.x * 16 + c);
        uint4 v1 = __ldg(in + (size_t)s1.x * 16 + c);
        uint4 v2 = __ldg(in + (size_t)s2.x * 16 + c);
        uint4 v3 = __ldg(in + (size_t)s3.x * 16 + c);
        gacc(acc, v0, __int_as_float(s0.y));
        gacc(acc, v1, __int_as_float(s1.y));
        gacc(acc, v2, __int_as_float(s2.y));
        gacc(acc, v3, __int_as_float(s3.y));
    }
    #pragma unroll 1
    for (; e < b1; e++) {
        int2 s0 = __ldg(&g_elist[e]);
        uint4 v0 = __ldg(in + (size_t)s0.x * 16 + c);
        gacc(acc, v0, __int_as_float(s0.y));
    }
    uint4 o;
    *(__half2*)&o.x = __floats2half2_rn(acc[0], acc[1]);
    *(__half2*)&o.y = __floats2half2_rn(acc[2], acc[3]);
    *(__half2*)&o.z = __floats2half2_rn(acc[4], acc[5]);
    *(__half2*)&o.w = __floats2half2_rn(acc[6], acc[7]);
    agg[(size_t)row * 16 + c] = o;
}

// ---------------- fp16 warp-MMA GEMM, cp.async pipelined (round-9 config) ----
#define GB_A0   1024
#define GB_W    (GB_A0 + 3 * 16384)
#define GB_SMEM (GB_W + 65536)

__device__ __forceinline__ void cpA(uint32_t sbase, int buf, int tid, int r0,
                                    int n, int c,
                                    const __half* __restrict__ Arel,
                                    const __half* __restrict__ Aroot)
{
    const char* As = (const char*)((c < 2) ? Arel : Aroot);
    int off = (c & 1) * 128;
    #pragma unroll
    for (int i = 0; i < 4; i++) {
        int q = tid + i * 256;
        int row = q >> 3, u = q & 7;
        int gr = r0 + row;
        cp16(sbase + GB_A0 + buf * 16384 + row * 128 + (((u ^ (row & 7)) & 7) << 4),
             As + (size_t)gr * 256 + off + u * 16, gr < n);
    }
}

template <int MODE>
__global__ __launch_bounds__(256) void gemm_h_kernel(
    const __half* __restrict__ Arel, const __half* __restrict__ Aroot,
    const __half* __restrict__ wh, const float* __restrict__ brel,
    const float* __restrict__ resid, void* __restrict__ outv, int n)
{
    extern __shared__ char smem[];
    uint32_t sbase = smem_u32(smem);
    int tid = threadIdx.x, wid = tid >> 5, lane = tid & 31;
    int wm = wid & 3, wn = wid >> 2;
    int r0 = blockIdx.x * 128;

    if (tid < 128) ((float*)smem)[tid] = __ldg(brel + tid);

    #pragma unroll
    for (int i = 0; i < 16; i++) {
        int q = tid + i * 256;
        int row = q >> 5, uu = q & 31;
        int phys = (uu & 0x18) | ((uu ^ row) & 7);
        cp16(sbase + GB_W + row * 512 + phys * 16,
             (const char*)wh + (size_t)row * 512 + uu * 16, true);
    }
    cpA(sbase, 0, tid, r0, n, 0, Arel, Aroot);
    CP_COMMIT();
    cpA(sbase, 1, tid, r0, n, 1, Arel, Aroot);
    CP_COMMIT();

    float acc[2][8][4];
    #pragma unroll
    for (int t = 0; t < 2; t++)
        #pragma unroll
        for (int u = 0; u < 8; u++)
            #pragma unroll
            for (int v = 0; v < 4; v++) acc[t][u][v] = 0.f;

    int j = lane & 7, grp = lane >> 3;
    int a_row = wm * 32 + ((grp & 1) << 3) + j;
    int a_ub  = grp >> 1;
    int b_row = wn * 64 + (((grp >> 1) & 1) << 3) + j;
    int b_r7  = b_row & 7;
    int b_ub  = grp & 1;

    #pragma unroll 1
    for (int c = 0; c < 4; c++) {
        if (c < 3) { CP_WAIT(1); } else { CP_WAIT(0); }
        __syncthreads();
        if (c < 2) {
            cpA(sbase, (c + 2) % 3, tid, r0, n, c + 2, Arel, Aroot);
            CP_COMMIT();
        }
        uint32_t aB = sbase + GB_A0 + (uint32_t)(c % 3) * 16384;
        #pragma unroll
        for (int ks = 0; ks < 4; ks++) {
            uint4 af[2];
            #pragma unroll
            for (int t = 0; t < 2; t++) {
                int row = a_row + t * 16;
                int u = ks * 2 + a_ub;
                ldsm4(af[t], aB + row * 128 + (((u ^ (row & 7)) & 7) << 4));
            }
            uint4 bf[4];
            #pragma unroll
            for (int p = 0; p < 4; p++) {
                int row = b_row + p * 16;
                int uu = c * 8 + ks * 2 + b_ub;
                int phys = (uu & 0x18) | ((uu ^ b_r7) & 7);
                ldsm4(bf[p], sbase + GB_W + row * 512 + phys * 16);
            }
            #pragma unroll
            for (int t = 0; t < 2; t++)
                #pragma unroll
                for (int u = 0; u < 8; u++) {
                    int p = u >> 1;
                    uint32_t b0 = (u & 1) ? bf[p].z : bf[p].x;
                    uint32_t b1 = (u & 1) ? bf[p].w : bf[p].y;
                    mma16816(acc[t][u], af[t], b0, b1);
                }
        }
    }

    const float* bias = (const float*)smem;
    int rb = r0 + wm * 32 + (lane >> 2);
    int cb = wn * 64 + ((lane & 3) << 1);
    #pragma unroll
    for (int t = 0; t < 2; t++) {
        #pragma unroll
        for (int u = 0; u < 8; u++) {
            int cc = cb + u * 8;
            float b0v = bias[cc], b1v = bias[cc + 1];
            #pragma unroll
            for (int h = 0; h < 2; h++) {
                int r = rb + t * 16 + h * 8;
                if (r >= n) continue;
                float vx = acc[t][u][h * 2 + 0] + b0v;
                float vy = acc[t][u][h * 2 + 1] + b1v;
                if (MODE == 0) {
                    vx = (vx >= 0.f) ? vx : 0.1f * vx;
                    vy = (vy >= 0.f) ? vy : 0.1f * vy;
                    __half2* op = (__half2*)((__half*)outv + (size_t)r * W + cc);
                    *op = __floats2half2_rn(vx, vy);
                } else {
                    float2 rr = *(const float2*)(resid + (size_t)r * W + cc);
                    vx += rr.x; vy += rr.y;
                    *(float2*)((float*)outv + (size_t)r * W + cc) =
                        make_float2(vx, vy);
                }
            }
        }
    }
}

// ---------------- launch -----------------------------------------------------
extern "C" void kernel_launch(void* const* d_in, const int* in_sizes, int n_in,
                              void* d_out, int out_size)
{
    const float* x      = (const float*)d_in[0];
    const int*   eidx   = (const int*)d_in[1];
    const float* ew     = (const float*)d_in[2];
    const int*   bmap   = (const int*)d_in[3];
    const float* gnw    = (const float*)d_in[4];
    const float* gnb    = (const float*)d_in[5];
    const float* msc    = (const float*)d_in[6];
    const float* Wrel1  = (const float*)d_in[7];
    const float* brel1  = (const float*)d_in[8];
    const float* Wroot1 = (const float*)d_in[9];
    const float* Wrel2  = (const float*)d_in[10];
    const float* brel2  = (const float*)d_in[11];
    const float* Wroot2 = (const float*)d_in[12];
    float* out = (float*)d_out;

    int n = in_sizes[0] / W;
    int E = in_sizes[2];
    const int* src = eidx;
    const int* dst = eidx + E;

    void *p_xnh, *p_aggh, *p_h1h, *p_wh;
    cudaGetSymbolAddress(&p_xnh, g_xnh);
    cudaGetSymbolAddress(&p_aggh, g_aggh);
    cudaGetSymbolAddress(&p_h1h, g_h1h);
    cudaGetSymbolAddress(&p_wh, g_wh);
    __half* xnh  = (__half*)p_xnh;
    __half* aggh = (__half*)p_aggh;
    __half* h1h  = (__half*)p_h1h;
    __half* wh   = (__half*)p_wh;

    cudaFuncSetAttribute(gemm_h_kernel<0>,
                         cudaFuncAttributeMaxDynamicSharedMemorySize, GB_SMEM);
    cudaFuncSetAttribute(gemm_h_kernel<1>,
                         cudaFuncAttributeMaxDynamicSharedMemorySize, GB_SMEM);

    // K1: stats || hist || wprep
    int nbS = (n + 255) / 256;
    int nbH = (E + 1023) / 1024;
    int nbW = 128;
    k1_kernel<<<nbS + nbH + nbW, 256>>>(x, bmap, n, dst, E,
                                        Wrel1, Wroot1, Wrel2, Wroot2, nbS, nbH);

    // K2: finalize || scan1
    int n4 = (n + 3) / 4;
    int nscan = (n4 + 1023) / 1024;
    int nbF = (G * W) / 256;
    k2_kernel<<<nbF + nscan, 256>>>(gnw, gnb, msc, n4, nbF);

    // K3: scan3 (inline scan2)
    k3_kernel<<<nscan, 256>>>(n4, nscan, n);

    // K4: place || norm
    int nbP = (E + 1023) / 1024;
    int total4 = n * 32;
    int nbN = (total4 + 255) / 256;
    k4_kernel<<<nbP + nbN, 256>>>(src, dst, ew, E,
                                  (const float4*)x, bmap, total4, nbP);

    // conv1: gather + GEMM(+LeakyReLU) -> fp16 h1
    int gwBlocks = (n * 16 + 255) / 256;
    gather_kernel<<<gwBlocks, 256>>>((const uint4*)xnh, (uint4*)aggh, n);
    int gBlocks = (n + 127) / 128;
    gemm_h_kernel<0><<<gBlocks, 256, GB_SMEM>>>(
        aggh, xnh, wh, brel1, nullptr, h1h, n);

    // conv2: gather + GEMM(+residual) -> fp32 out
    gather_kernel<<<gwBlocks, 256>>>((const uint4*)h1h, (uint4*)aggh, n);
    gemm_h_kernel<1><<<gBlocks, 256, GB_SMEM>>>(
        aggh, h1h, wh + 128 * 256, brel2, x, out, n);
}

// round 14
// speedup vs baseline: 1.2634x; 1.1491x over previous
#include <cuda_runtime.h>
#include <cuda_fp16.h>
#include <cstdint>

#define W 128
#define G 64
#define MAXN 100000
#define MAXE 625000
#define EPS 1e-5f

// ---------------- scratch (static device globals; zero-initialized) ----------
__device__ __half g_xnh[MAXN * W];
__device__ __half g_aggh[MAXN * W];
__device__ __half g_h1h[MAXN * W];
__device__ __half g_wh[2 * 128 * 256];
__device__ float g_sum[G * W];        // self-cleaned by finalize
__device__ float g_sumsq[G * W];      // self-cleaned by finalize
__device__ float g_cnt[G];            // self-cleaned by finalize
__device__ float g_alpha[G * W];
__device__ float g_beta[G * W];
__device__ int   g_deg[MAXN];         // self-cleaned by scan3
__device__ int   g_base[MAXN + 4];
__device__ int   g_cur[MAXN];         // self-cleaned by gather
__device__ int2  g_elist[MAXE];
__device__ int   g_bsum[64];

// ---------------- PTX helpers (sm_80/90 baseline only) -----------------------
__device__ __forceinline__ uint32_t smem_u32(const void* p) {
    uint32_t a;
    asm("{ .reg .u64 t; cvta.to.shared.u64 t, %1; cvt.u32.u64 %0, t; }"
        : "=r"(a) : "l"(p));
    return a;
}
__device__ __forceinline__ void ldsm4(uint4& r, uint32_t addr) {
    asm volatile("ldmatrix.sync.aligned.m8n8.x4.shared.b16 {%0,%1,%2,%3}, [%4];"
                 : "=r"(r.x), "=r"(r.y), "=r"(r.z), "=r"(r.w) : "r"(addr));
}
__device__ __forceinline__ void mma16816(float* d, const uint4& a,
                                         uint32_t b0, uint32_t b1) {
    asm volatile(
        "mma.sync.aligned.m16n8k16.row.col.f32.f16.f16.f32 "
        "{%0,%1,%2,%3}, {%4,%5,%6,%7}, {%8,%9}, {%0,%1,%2,%3};"
        : "+f"(d[0]), "+f"(d[1]), "+f"(d[2]), "+f"(d[3])
        : "r"(a.x), "r"(a.y), "r"(a.z), "r"(a.w), "r"(b0), "r"(b1));
}
__device__ __forceinline__ void cp16(uint32_t dst, const void* src, bool pred) {
    int sz = pred ? 16 : 0;
    asm volatile("cp.async.cg.shared.global [%0], [%1], 16, %2;"
                 :: "r"(dst), "l"(src), "r"(sz) : "memory");
}
#define CP_COMMIT() asm volatile("cp.async.commit_group;" ::: "memory")
#define CP_WAIT(N)  asm volatile("cp.async.wait_group %0;" :: "n"(N) : "memory")

// ================= K1: stats || hist || wprep (grid-partitioned) =============
__global__ __launch_bounds__(256) void k1_kernel(
    const float* __restrict__ x, const int* __restrict__ bmap, int n,
    const int* __restrict__ dst, int E,
    const float* __restrict__ Wr1, const float* __restrict__ Wo1,
    const float* __restrict__ Wr2, const float* __restrict__ Wo2,
    int nbS, int nbH)
{
    int b = blockIdx.x, tid = threadIdx.x;
    if (b < nbS) {
        int f = tid & 127, sub = tid >> 7;
        int n0 = b * 256 + sub * 128;
        if (n0 >= n) return;
        int n1 = min(n0 + 128, n);
        float s = 0.f, ss = 0.f;
        int curg = __ldg(bmap + n0);
        int r = n0;
        // 4-row unrolled: loads issued before group checks (MLP 4)
        #pragma unroll 1
        for (; r + 4 <= n1; r += 4) {
            int gA = __ldg(bmap + r);
            int gB = __ldg(bmap + r + 1);
            int gC = __ldg(bmap + r + 2);
            int gD = __ldg(bmap + r + 3);
            float vA = x[(size_t)r * W + f];
            float vB = x[(size_t)(r + 1) * W + f];
            float vC = x[(size_t)(r + 2) * W + f];
            float vD = x[(size_t)(r + 3) * W + f];
            if (gA != curg) {
                atomicAdd(&g_sum[curg * W + f], s);
                atomicAdd(&g_sumsq[curg * W + f], ss);
                s = 0.f; ss = 0.f; curg = gA;
            }
            s += vA; ss += vA * vA;
            if (gB != curg) {
                atomicAdd(&g_sum[curg * W + f], s);
                atomicAdd(&g_sumsq[curg * W + f], ss);
                s = 0.f; ss = 0.f; curg = gB;
            }
            s += vB; ss += vB * vB;
            if (gC != curg) {
                atomicAdd(&g_sum[curg * W + f], s);
                atomicAdd(&g_sumsq[curg * W + f], ss);
                s = 0.f; ss = 0.f; curg = gC;
            }
            s += vC; ss += vC * vC;
            if (gD != curg) {
                atomicAdd(&g_sum[curg * W + f], s);
                atomicAdd(&g_sumsq[curg * W + f], ss);
                s = 0.f; ss = 0.f; curg = gD;
            }
            s += vD; ss += vD * vD;
        }
        #pragma unroll 1
        for (; r < n1; r++) {
            int g = __ldg(bmap + r);
            if (g != curg) {
                atomicAdd(&g_sum[curg * W + f], s);
                atomicAdd(&g_sumsq[curg * W + f], ss);
                s = 0.f; ss = 0.f; curg = g;
            }
            float v = x[(size_t)r * W + f];
            s += v; ss += v * v;
        }
        atomicAdd(&g_sum[curg * W + f], s);
        atomicAdd(&g_sumsq[curg * W + f], ss);
        if (f == 0) {
            int cg = __ldg(bmap + n0), rs = n0;
            for (int rr = n0; rr < n1; rr++) {
                int g = __ldg(bmap + rr);
                if (g != cg) {
                    atomicAdd(&g_cnt[cg], (float)(rr - rs));
                    cg = g; rs = rr;
                }
            }
            atomicAdd(&g_cnt[cg], (float)(n1 - rs));
        }
    } else if (b < nbS + nbH) {
        int i4 = (b - nbS) * 256 + tid;
        int e = i4 * 4;
        if (e + 3 < E) {
            int4 d = __ldg((const int4*)dst + i4);
            atomicAdd(&g_deg[d.x], 1);
            atomicAdd(&g_deg[d.y], 1);
            atomicAdd(&g_deg[d.z], 1);
            atomicAdd(&g_deg[d.w], 1);
        } else {
            for (int j2 = 0; j2 < 4; j2++)
                if (e + j2 < E) atomicAdd(&g_deg[__ldg(dst + e + j2)], 1);
        }
    } else {
        int idx = (b - nbS - nbH) * 256 + tid;
        int conv = idx >> 14;
        int rem  = idx & 16383;
        int row  = rem >> 7;
        int c2   = rem & 127;
        const float* Wr = conv ? Wr2 : Wr1;
        const float* Wo = conv ? Wo2 : Wo1;
        const float* s = (c2 < 64) ? (Wr + row * 128 + c2 * 2)
                                   : (Wo + row * 128 + (c2 - 64) * 2);
        float2 v = *(const float2*)s;
        ((__half2*)(g_wh + (size_t)conv * 128 * 256 + row * 256))[c2] =
            __floats2half2_rn(v.x, v.y);
    }
}

// ================= K2: finalize || scan1 =====================================
__global__ __launch_bounds__(256) void k2_kernel(
    const float* __restrict__ gnw, const float* __restrict__ gnb,
    const float* __restrict__ msc, int n4, int nbF)
{
    int b = blockIdx.x, tid = threadIdx.x, lane = tid & 31, wid = tid >> 5;
    if (b < nbF) {
        int idx = b * 256 + tid;
        int g = idx >> 7, f = idx & 127;
        float cnt  = g_cnt[g];
        float inv  = (cnt > 0.f) ? (1.f / cnt) : 0.f;
        float mean = g_sum[idx] * inv;
        float q    = g_sumsq[idx] * inv;
        g_sum[idx] = 0.f;
        g_sumsq[idx] = 0.f;
        float m    = __ldg(msc + f);
        float var  = q - mean * mean * m * (2.f - m);
        float istd = rsqrtf(var + EPS);
        float a    = __ldg(gnw + f) * istd;
        g_alpha[idx] = a;
        g_beta[idx]  = __ldg(gnb + f) - a * m * mean;
        __syncthreads();
        if (f == 0) g_cnt[g] = 0.f;
    } else {
        __shared__ int wS[8];
        int sb = b - nbF;
        const int4* dp = (const int4*)g_deg;
        int i4 = sb * 1024 + tid * 4;
        int s = 0;
        #pragma unroll
        for (int j2 = 0; j2 < 4; j2++) {
            if (i4 + j2 < n4) {
                int4 v = dp[i4 + j2];
                s += v.x + v.y + v.z + v.w;
            }
        }
        #pragma unroll
        for (int o = 16; o > 0; o >>= 1) s += __shfl_down_sync(~0u, s, o);
        if (lane == 0) wS[wid] = s;
        __syncthreads();
        if (tid == 0) {
            int t = 0;
            #pragma unroll
            for (int k = 0; k < 8; k++) t += wS[k];
            g_bsum[sb] = t;
        }
    }
}

// ================= K3: scan3 (with inline scan2 over g_bsum) =================
__global__ __launch_bounds__(256) void k3_kernel(int n4, int nscan, int n)
{
    __shared__ int wS[8];
    __shared__ int boff;
    int b = blockIdx.x, tid = threadIdx.x, lane = tid & 31, wid = tid >> 5;
    if (tid == 0) {
        int run = 0;
        for (int i = 0; i < b; i++) run += g_bsum[i];
        boff = run;
        if (b == 0) {
            int tot = 0;
            for (int i = 0; i < nscan; i++) tot += g_bsum[i];
            g_base[n] = tot;
        }
    }
    int4* dp = (int4*)g_deg;
    int i4 = b * 1024 + tid * 4;
    int4 v[4];
    int s = 0;
    #pragma unroll
    for (int j2 = 0; j2 < 4; j2++) {
        v[j2] = make_int4(0, 0, 0, 0);
        if (i4 + j2 < n4) {
            v[j2] = dp[i4 + j2];
            dp[i4 + j2] = make_int4(0, 0, 0, 0);
        }
        s += v[j2].x + v[j2].y + v[j2].z + v[j2].w;
    }
    int x = s;
    #pragma unroll
    for (int o = 1; o < 32; o <<= 1) {
        int y = __shfl_up_sync(~0u, x, o);
        if (lane >= o) x += y;
    }
    if (lane == 31) wS[wid] = x;
    __syncthreads();
    int woff = 0;
    #pragma unroll
    for (int k = 0; k < 8; k++)
        if (k < wid) woff += wS[k];
    int run = boff + woff + x - s;
    int4* bp = (int4*)g_base;
    #pragma unroll
    for (int j2 = 0; j2 < 4; j2++) {
        if (i4 + j2 < n4) {
            int4 o;
            o.x = run; run += v[j2].x;
            o.y = run; run += v[j2].y;
            o.z = run; run += v[j2].z;
            o.w = run; run += v[j2].w;
            bp[i4 + j2] = o;
        }
    }
}

// ================= K4: place || norm (norm 4x ILP) ===========================
__global__ __launch_bounds__(256) void k4_kernel(
    const int* __restrict__ src, const int* __restrict__ dst,
    const float* __restrict__ ew, int E,
    const float4* __restrict__ x, const int* __restrict__ bmap, int total4,
    int nbP)
{
    int b = blockIdx.x, tid = threadIdx.x;
    if (b < nbP) {
        int i4 = b * 256 + tid;
        int e = i4 * 4;
        if (e + 3 < E) {
            int4 sv = __ldg((const int4*)src + i4);
            int4 dv = __ldg((const int4*)dst + i4);
            float4 wv = __ldg((const float4*)ew + i4);
            int p;
            p = g_base[dv.x] + atomicAdd(&g_cur[dv.x], 1);
            g_elist[p] = make_int2(sv.x, __float_as_int(wv.x));
            p = g_base[dv.y] + atomicAdd(&g_cur[dv.y], 1);
            g_elist[p] = make_int2(sv.y, __float_as_int(wv.y));
            p = g_base[dv.z] + atomicAdd(&g_cur[dv.z], 1);
            g_elist[p] = make_int2(sv.z, __float_as_int(wv.z));
            p = g_base[dv.w] + atomicAdd(&g_cur[dv.w], 1);
            g_elist[p] = make_int2(sv.w, __float_as_int(wv.w));
        } else {
            for (int j2 = 0; j2 < 4; j2++) {
                int ee = e + j2;
                if (ee < E) {
                    int d = __ldg(dst + ee);
                    int p = g_base[d] + atomicAdd(&g_cur[d], 1);
                    g_elist[p] = make_int2(__ldg(src + ee),
                                           __float_as_int(__ldg(ew + ee)));
                }
            }
        }
    } else {
        // norm: 4 consecutive float4s per thread, loads issued first (MLP 4)
        int base = ((b - nbP) * 256 + tid) * 4;
        if (base >= total4) return;
        float4 xv[4];
        #pragma unroll
        for (int k = 0; k < 4; k++) xv[k] = __ldg(x + base + k);
        #pragma unroll
        for (int k = 0; k < 4; k++) {
            int idx = base + k;
            int r = idx >> 5, c = idx & 31;
            int g = __ldg(bmap + r);
            float4 a = ((const float4*)g_alpha)[g * 32 + c];
            float4 bb = ((const float4*)g_beta)[g * 32 + c];
            float ox = fmaf(a.x, xv[k].x, bb.x);
            float oy = fmaf(a.y, xv[k].y, bb.y);
            float oz = fmaf(a.z, xv[k].z, bb.z);
            float ow = fmaf(a.w, xv[k].w, bb.w);
            uint2 o;
            *(__half2*)&o.x = __floats2half2_rn(ox, oy);
            *(__half2*)&o.y = __floats2half2_rn(oz, ow);
            ((uint2*)g_xnh)[idx] = o;
        }
    }
}

// ---------------- gather: half-warp per row, uint4 loads, 4-edge ILP ---------
__device__ __forceinline__ void gacc(float* acc, uint4 v, float w) {
    float2 p0 = __half22float2(*(__half2*)&v.x);
    float2 p1 = __half22float2(*(__half2*)&v.y);
    float2 p2 = __half22float2(*(__half2*)&v.z);
    float2 p3 = __half22float2(*(__half2*)&v.w);
    acc[0] = fmaf(w, p0.x, acc[0]); acc[1] = fmaf(w, p0.y, acc[1]);
    acc[2] = fmaf(w, p1.x, acc[2]); acc[3] = fmaf(w, p1.y, acc[3]);
    acc[4] = fmaf(w, p2.x, acc[4]); acc[5] = fmaf(w, p2.y, acc[5]);
    acc[6] = fmaf(w, p3.x, acc[6]); acc[7] = fmaf(w, p3.y, acc[7]);
}

__global__ __launch_bounds__(256) void gather_kernel(
    const uint4* __restrict__ in, uint4* __restrict__ agg, int n)
{
    int row = (blockIdx.x * 256 + threadIdx.x) >> 4;   // one half-warp per row
    if (row >= n) return;
    int c = threadIdx.x & 15;
    int b0 = g_base[row], b1 = g_base[row + 1];
    if (c == 0) g_cur[row] = 0;                        // self-clean for replay
    float acc[8];
    #pragma unroll
    for (int i = 0; i < 8; i++) acc[i] = 0.f;
    int e = b0;
    #pragma unroll 1
    for (; e + 4 <= b1; e += 4) {
        int2 s0 = __ldg(&g_elist[e]);
        int2 s1 = __ldg(&g_elist[e + 1]);
        int2 s2 = __ldg(&g_elist[e + 2]);
        int2 s3 = __ldg(&g_elist[e + 3]);
        uint4 v0 = __ldg(in + (size_t)s0.x * 16 + c);
        uint4 v1 = __ldg(in + (size_t)s1.x * 16 + c);
        uint4 v2 = __ldg(in + (size_t)s2.x * 16 + c);
        uint4 v3 = __ldg(in + (size_t)s3.x * 16 + c);
        gacc(acc, v0, __int_as_float(s0.y));
        gacc(acc, v1, __int_as_float(s1.y));
        gacc(acc, v2, __int_as_float(s2.y));
        gacc(acc, v3, __int_as_float(s3.y));
    }
    #pragma unroll 1
    for (; e < b1; e++) {
        int2 s0 = __ldg(&g_elist[e]);
        uint4 v0 = __ldg(in + (size_t)s0.x * 16 + c);
        gacc(acc, v0, __int_as_float(s0.y));
    }
    uint4 o;
    *(__half2*)&o.x = __floats2half2_rn(acc[0], acc[1]);
    *(__half2*)&o.y = __floats2half2_rn(acc[2], acc[3]);
    *(__half2*)&o.z = __floats2half2_rn(acc[4], acc[5]);
    *(__half2*)&o.w = __floats2half2_rn(acc[6], acc[7]);
    agg[(size_t)row * 16 + c] = o;
}

// ---------------- fp16 warp-MMA GEMM, cp.async pipelined (round-9 config) ----
#define GB_A0   1024
#define GB_W    (GB_A0 + 3 * 16384)
#define GB_SMEM (GB_W + 65536)

__device__ __forceinline__ void cpA(uint32_t sbase, int buf, int tid, int r0,
                                    int n, int c,
                                    const __half* __restrict__ Arel,
                                    const __half* __restrict__ Aroot)
{
    const char* As = (const char*)((c < 2) ? Arel : Aroot);
    int off = (c & 1) * 128;
    #pragma unroll
    for (int i = 0; i < 4; i++) {
        int q = tid + i * 256;
        int row = q >> 3, u = q & 7;
        int gr = r0 + row;
        cp16(sbase + GB_A0 + buf * 16384 + row * 128 + (((u ^ (row & 7)) & 7) << 4),
             As + (size_t)gr * 256 + off + u * 16, gr < n);
    }
}

template <int MODE>
__global__ __launch_bounds__(256) void gemm_h_kernel(
    const __half* __restrict__ Arel, const __half* __restrict__ Aroot,
    const __half* __restrict__ wh, const float* __restrict__ brel,
    const float* __restrict__ resid, void* __restrict__ outv, int n)
{
    extern __shared__ char smem[];
    uint32_t sbase = smem_u32(smem);
    int tid = threadIdx.x, wid = tid >> 5, lane = tid & 31;
    int wm = wid & 3, wn = wid >> 2;
    int r0 = blockIdx.x * 128;

    if (tid < 128) ((float*)smem)[tid] = __ldg(brel + tid);

    #pragma unroll
    for (int i = 0; i < 16; i++) {
        int q = tid + i * 256;
        int row = q >> 5, uu = q & 31;
        int phys = (uu & 0x18) | ((uu ^ row) & 7);
        cp16(sbase + GB_W + row * 512 + phys * 16,
             (const char*)wh + (size_t)row * 512 + uu * 16, true);
    }
    cpA(sbase, 0, tid, r0, n, 0, Arel, Aroot);
    CP_COMMIT();
    cpA(sbase, 1, tid, r0, n, 1, Arel, Aroot);
    CP_COMMIT();

    float acc[2][8][4];
    #pragma unroll
    for (int t = 0; t < 2; t++)
        #pragma unroll
        for (int u = 0; u < 8; u++)
            #pragma unroll
            for (int v = 0; v < 4; v++) acc[t][u][v] = 0.f;

    int j = lane & 7, grp = lane >> 3;
    int a_row = wm * 32 + ((grp & 1) << 3) + j;
    int a_ub  = grp >> 1;
    int b_row = wn * 64 + (((grp >> 1) & 1) << 3) + j;
    int b_r7  = b_row & 7;
    int b_ub  = grp & 1;

    #pragma unroll 1
    for (int c = 0; c < 4; c++) {
        if (c < 3) { CP_WAIT(1); } else { CP_WAIT(0); }
        __syncthreads();
        if (c < 2) {
            cpA(sbase, (c + 2) % 3, tid, r0, n, c + 2, Arel, Aroot);
            CP_COMMIT();
        }
        uint32_t aB = sbase + GB_A0 + (uint32_t)(c % 3) * 16384;
        #pragma unroll
        for (int ks = 0; ks < 4; ks++) {
            uint4 af[2];
            #pragma unroll
            for (int t = 0; t < 2; t++) {
                int row = a_row + t * 16;
                int u = ks * 2 + a_ub;
                ldsm4(af[t], aB + row * 128 + (((u ^ (row & 7)) & 7) << 4));
            }
            uint4 bf[4];
            #pragma unroll
            for (int p = 0; p < 4; p++) {
                int row = b_row + p * 16;
                int uu = c * 8 + ks * 2 + b_ub;
                int phys = (uu & 0x18) | ((uu ^ b_r7) & 7);
                ldsm4(bf[p], sbase + GB_W + row * 512 + phys * 16);
            }
            #pragma unroll
            for (int t = 0; t < 2; t++)
                #pragma unroll
                for (int u = 0; u < 8; u++) {
                    int p = u >> 1;
                    uint32_t b0 = (u & 1) ? bf[p].z : bf[p].x;
                    uint32_t b1 = (u & 1) ? bf[p].w : bf[p].y;
                    mma16816(acc[t][u], af[t], b0, b1);
                }
        }
    }

    const float* bias = (const float*)smem;
    int rb = r0 + wm * 32 + (lane >> 2);
    int cb = wn * 64 + ((lane & 3) << 1);
    #pragma unroll
    for (int t = 0; t < 2; t++) {
        #pragma unroll
        for (int u = 0; u < 8; u++) {
            int cc = cb + u * 8;
            float b0v = bias[cc], b1v = bias[cc + 1];
            #pragma unroll
            for (int h = 0; h < 2; h++) {
                int r = rb + t * 16 + h * 8;
                if (r >= n) continue;
                float vx = acc[t][u][h * 2 + 0] + b0v;
                float vy = acc[t][u][h * 2 + 1] + b1v;
                if (MODE == 0) {
                    vx = (vx >= 0.f) ? vx : 0.1f * vx;
                    vy = (vy >= 0.f) ? vy : 0.1f * vy;
                    __half2* op = (__half2*)((__half*)outv + (size_t)r * W + cc);
                    *op = __floats2half2_rn(vx, vy);
                } else {
                    float2 rr = *(const float2*)(resid + (size_t)r * W + cc);
                    vx += rr.x; vy += rr.y;
                    *(float2*)((float*)outv + (size_t)r * W + cc) =
                        make_float2(vx, vy);
                }
            }
        }
    }
}

// ---------------- launch -----------------------------------------------------
extern "C" void kernel_launch(void* const* d_in, const int* in_sizes, int n_in,
                              void* d_out, int out_size)
{
    const float* x      = (const float*)d_in[0];
    const int*   eidx   = (const int*)d_in[1];
    const float* ew     = (const float*)d_in[2];
    const int*   bmap   = (const int*)d_in[3];
    const float* gnw    = (const float*)d_in[4];
    const float* gnb    = (const float*)d_in[5];
    const float* msc    = (const float*)d_in[6];
    const float* Wrel1  = (const float*)d_in[7];
    const float* brel1  = (const float*)d_in[8];
    const float* Wroot1 = (const float*)d_in[9];
    const float* Wrel2  = (const float*)d_in[10];
    const float* brel2  = (const float*)d_in[11];
    const float* Wroot2 = (const float*)d_in[12];
    float* out = (float*)d_out;

    int n = in_sizes[0] / W;
    int E = in_sizes[2];
    const int* src = eidx;
    const int* dst = eidx + E;

    void *p_xnh, *p_aggh, *p_h1h, *p_wh;
    cudaGetSymbolAddress(&p_xnh, g_xnh);
    cudaGetSymbolAddress(&p_aggh, g_aggh);
    cudaGetSymbolAddress(&p_h1h, g_h1h);
    cudaGetSymbolAddress(&p_wh, g_wh);
    __half* xnh  = (__half*)p_xnh;
    __half* aggh = (__half*)p_aggh;
    __half* h1h  = (__half*)p_h1h;
    __half* wh   = (__half*)p_wh;

    cudaFuncSetAttribute(gemm_h_kernel<0>,
                         cudaFuncAttributeMaxDynamicSharedMemorySize, GB_SMEM);
    cudaFuncSetAttribute(gemm_h_kernel<1>,
                         cudaFuncAttributeMaxDynamicSharedMemorySize, GB_SMEM);

    // K1: stats || hist || wprep
    int nbS = (n + 255) / 256;
    int nbH = (E + 1023) / 1024;
    int nbW = 128;
    k1_kernel<<<nbS + nbH + nbW, 256>>>(x, bmap, n, dst, E,
                                        Wrel1, Wroot1, Wrel2, Wroot2, nbS, nbH);

    // K2: finalize || scan1
    int n4 = (n + 3) / 4;
    int nscan = (n4 + 1023) / 1024;
    int nbF = (G * W) / 256;
    k2_kernel<<<nbF + nscan, 256>>>(gnw, gnb, msc, n4, nbF);

    // K3: scan3 (inline scan2)
    k3_kernel<<<nscan, 256>>>(n4, nscan, n);

    // K4: place || norm (norm 4x ILP)
    int nbP = (E + 1023) / 1024;
    int total4 = n * 32;
    int nbN = (total4 / 4 + 255) / 256;
    k4_kernel<<<nbP + nbN, 256>>>(src, dst, ew, E,
                                  (const float4*)x, bmap, total4, nbP);

    // conv1: gather + GEMM(+LeakyReLU) -> fp16 h1
    int gwBlocks = (n * 16 + 255) / 256;
    gather_kernel<<<gwBlocks, 256>>>((const uint4*)xnh, (uint4*)aggh, n);
    int gBlocks = (n + 127) / 128;
    gemm_h_kernel<0><<<gBlocks, 256, GB_SMEM>>>(
        aggh, xnh, wh, brel1, nullptr, h1h, n);

    // conv2: gather + GEMM(+residual) -> fp32 out
    gather_kernel<<<gwBlocks, 256>>>((const uint4*)h1h, (uint4*)aggh, n);
    gemm_h_kernel<1><<<gBlocks, 256, GB_SMEM>>>(
        aggh, h1h, wh + 128 * 256, brel2, x, out, n);
}

// round 15
// speedup vs baseline: 1.3859x; 1.0970x over previous
#include <cuda_runtime.h>
#include <cuda_fp16.h>
#include <cstdint>

#define W 128
#define G 64
#define MAXN 100000
#define MAXE 625000
#define EPS 1e-5f

// ---------------- scratch (static device globals; zero-initialized) ----------
__device__ __half g_xnh[MAXN * W];
__device__ __half g_aggh[MAXN * W];
__device__ __half g_h1h[MAXN * W];
__device__ __half g_wh[2 * 128 * 256];
__device__ float g_sum[G * W];        // self-cleaned by finalize
__device__ float g_sumsq[G * W];      // self-cleaned by finalize
__device__ float g_cnt[G];            // self-cleaned by finalize
__device__ float g_alpha[G * W];
__device__ float g_beta[G * W];
__device__ int   g_deg[MAXN];         // self-cleaned by scan3
__device__ int   g_base[MAXN + 4];
__device__ int   g_cur[MAXN];         // self-cleaned by gather
__device__ int2  g_elist[MAXE];
__device__ int   g_bsum[64];

// ---------------- PTX helpers (sm_80/90 baseline only) -----------------------
__device__ __forceinline__ uint32_t smem_u32(const void* p) {
    uint32_t a;
    asm("{ .reg .u64 t; cvta.to.shared.u64 t, %1; cvt.u32.u64 %0, t; }"
        : "=r"(a) : "l"(p));
    return a;
}
__device__ __forceinline__ void ldsm4(uint4& r, uint32_t addr) {
    asm volatile("ldmatrix.sync.aligned.m8n8.x4.shared.b16 {%0,%1,%2,%3}, [%4];"
                 : "=r"(r.x), "=r"(r.y), "=r"(r.z), "=r"(r.w) : "r"(addr));
}
__device__ __forceinline__ void mma16816(float* d, const uint4& a,
                                         uint32_t b0, uint32_t b1) {
    asm volatile(
        "mma.sync.aligned.m16n8k16.row.col.f32.f16.f16.f32 "
        "{%0,%1,%2,%3}, {%4,%5,%6,%7}, {%8,%9}, {%0,%1,%2,%3};"
        : "+f"(d[0]), "+f"(d[1]), "+f"(d[2]), "+f"(d[3])
        : "r"(a.x), "r"(a.y), "r"(a.z), "r"(a.w), "r"(b0), "r"(b1));
}
__device__ __forceinline__ void cp16(uint32_t dst, const void* src, bool pred) {
    int sz = pred ? 16 : 0;
    asm volatile("cp.async.cg.shared.global [%0], [%1], 16, %2;"
                 :: "r"(dst), "l"(src), "r"(sz) : "memory");
}
#define CP_COMMIT() asm volatile("cp.async.commit_group;" ::: "memory")
#define CP_WAIT(N)  asm volatile("cp.async.wait_group %0;" :: "n"(N) : "memory")

// ================= K1: stats || hist || wprep (grid-partitioned) =============
__global__ __launch_bounds__(256) void k1_kernel(
    const float* __restrict__ x, const int* __restrict__ bmap, int n,
    const int* __restrict__ dst, int E,
    const float* __restrict__ Wr1, const float* __restrict__ Wo1,
    const float* __restrict__ Wr2, const float* __restrict__ Wo2,
    int nbS, int nbH)
{
    int b = blockIdx.x, tid = threadIdx.x;
    if (b < nbS) {
        int f = tid & 127, sub = tid >> 7;
        int n0 = b * 256 + sub * 128;
        if (n0 >= n) return;
        int n1 = min(n0 + 128, n);
        float s = 0.f, ss = 0.f;
        int curg = __ldg(bmap + n0);
        int r = n0;
        // 4-row unrolled: loads issued before group checks (MLP 4)
        #pragma unroll 1
        for (; r + 4 <= n1; r += 4) {
            int gA = __ldg(bmap + r);
            int gB = __ldg(bmap + r + 1);
            int gC = __ldg(bmap + r + 2);
            int gD = __ldg(bmap + r + 3);
            float vA = x[(size_t)r * W + f];
            float vB = x[(size_t)(r + 1) * W + f];
            float vC = x[(size_t)(r + 2) * W + f];
            float vD = x[(size_t)(r + 3) * W + f];
            if (gA != curg) {
                atomicAdd(&g_sum[curg * W + f], s);
                atomicAdd(&g_sumsq[curg * W + f], ss);
                s = 0.f; ss = 0.f; curg = gA;
            }
            s += vA; ss += vA * vA;
            if (gB != curg) {
                atomicAdd(&g_sum[curg * W + f], s);
                atomicAdd(&g_sumsq[curg * W + f], ss);
                s = 0.f; ss = 0.f; curg = gB;
            }
            s += vB; ss += vB * vB;
            if (gC != curg) {
                atomicAdd(&g_sum[curg * W + f], s);
                atomicAdd(&g_sumsq[curg * W + f], ss);
                s = 0.f; ss = 0.f; curg = gC;
            }
            s += vC; ss += vC * vC;
            if (gD != curg) {
                atomicAdd(&g_sum[curg * W + f], s);
                atomicAdd(&g_sumsq[curg * W + f], ss);
                s = 0.f; ss = 0.f; curg = gD;
            }
            s += vD; ss += vD * vD;
        }
        #pragma unroll 1
        for (; r < n1; r++) {
            int g = __ldg(bmap + r);
            if (g != curg) {
                atomicAdd(&g_sum[curg * W + f], s);
                atomicAdd(&g_sumsq[curg * W + f], ss);
                s = 0.f; ss = 0.f; curg = g;
            }
            float v = x[(size_t)r * W + f];
            s += v; ss += v * v;
        }
        atomicAdd(&g_sum[curg * W + f], s);
        atomicAdd(&g_sumsq[curg * W + f], ss);
        if (f == 0) {
            int cg = __ldg(bmap + n0), rs = n0;
            for (int rr = n0; rr < n1; rr++) {
                int g = __ldg(bmap + rr);
                if (g != cg) {
                    atomicAdd(&g_cnt[cg], (float)(rr - rs));
                    cg = g; rs = rr;
                }
            }
            atomicAdd(&g_cnt[cg], (float)(n1 - rs));
        }
    } else if (b < nbS + nbH) {
        int i4 = (b - nbS) * 256 + tid;
        int e = i4 * 4;
        if (e + 3 < E) {
            int4 d = __ldg((const int4*)dst + i4);
            atomicAdd(&g_deg[d.x], 1);
            atomicAdd(&g_deg[d.y], 1);
            atomicAdd(&g_deg[d.z], 1);
            atomicAdd(&g_deg[d.w], 1);
        } else {
            for (int j2 = 0; j2 < 4; j2++)
                if (e + j2 < E) atomicAdd(&g_deg[__ldg(dst + e + j2)], 1);
        }
    } else {
        int idx = (b - nbS - nbH) * 256 + tid;
        int conv = idx >> 14;
        int rem  = idx & 16383;
        int row  = rem >> 7;
        int c2   = rem & 127;
        const float* Wr = conv ? Wr2 : Wr1;
        const float* Wo = conv ? Wo2 : Wo1;
        const float* s = (c2 < 64) ? (Wr + row * 128 + c2 * 2)
                                   : (Wo + row * 128 + (c2 - 64) * 2);
        float2 v = *(const float2*)s;
        ((__half2*)(g_wh + (size_t)conv * 128 * 256 + row * 256))[c2] =
            __floats2half2_rn(v.x, v.y);
    }
}

// ================= K2: finalize || scan1 =====================================
__global__ __launch_bounds__(256) void k2_kernel(
    const float* __restrict__ gnw, const float* __restrict__ gnb,
    const float* __restrict__ msc, int n4, int nbF)
{
    int b = blockIdx.x, tid = threadIdx.x, lane = tid & 31, wid = tid >> 5;
    if (b < nbF) {
        int idx = b * 256 + tid;
        int g = idx >> 7, f = idx & 127;
        float cnt  = g_cnt[g];
        float inv  = (cnt > 0.f) ? (1.f / cnt) : 0.f;
        float mean = g_sum[idx] * inv;
        float q    = g_sumsq[idx] * inv;
        g_sum[idx] = 0.f;
        g_sumsq[idx] = 0.f;
        float m    = __ldg(msc + f);
        float var  = q - mean * mean * m * (2.f - m);
        float istd = rsqrtf(var + EPS);
        float a    = __ldg(gnw + f) * istd;
        g_alpha[idx] = a;
        g_beta[idx]  = __ldg(gnb + f) - a * m * mean;
        __syncthreads();
        if (f == 0) g_cnt[g] = 0.f;
    } else {
        __shared__ int wS[8];
        int sb = b - nbF;
        const int4* dp = (const int4*)g_deg;
        int i4 = sb * 1024 + tid * 4;
        int s = 0;
        #pragma unroll
        for (int j2 = 0; j2 < 4; j2++) {
            if (i4 + j2 < n4) {
                int4 v = dp[i4 + j2];
                s += v.x + v.y + v.z + v.w;
            }
        }
        #pragma unroll
        for (int o = 16; o > 0; o >>= 1) s += __shfl_down_sync(~0u, s, o);
        if (lane == 0) wS[wid] = s;
        __syncthreads();
        if (tid == 0) {
            int t = 0;
            #pragma unroll
            for (int k = 0; k < 8; k++) t += wS[k];
            g_bsum[sb] = t;
        }
    }
}

// ================= K3: scan3 (with inline scan2 over g_bsum) =================
__global__ __launch_bounds__(256) void k3_kernel(int n4, int nscan, int n)
{
    __shared__ int wS[8];
    __shared__ int boff;
    int b = blockIdx.x, tid = threadIdx.x, lane = tid & 31, wid = tid >> 5;
    if (tid == 0) {
        int run = 0;
        for (int i = 0; i < b; i++) run += g_bsum[i];
        boff = run;
        if (b == 0) {
            int tot = 0;
            for (int i = 0; i < nscan; i++) tot += g_bsum[i];
            g_base[n] = tot;
        }
    }
    int4* dp = (int4*)g_deg;
    int i4 = b * 1024 + tid * 4;
    int4 v[4];
    int s = 0;
    #pragma unroll
    for (int j2 = 0; j2 < 4; j2++) {
        v[j2] = make_int4(0, 0, 0, 0);
        if (i4 + j2 < n4) {
            v[j2] = dp[i4 + j2];
            dp[i4 + j2] = make_int4(0, 0, 0, 0);
        }
        s += v[j2].x + v[j2].y + v[j2].z + v[j2].w;
    }
    int x = s;
    #pragma unroll
    for (int o = 1; o < 32; o <<= 1) {
        int y = __shfl_up_sync(~0u, x, o);
        if (lane >= o) x += y;
    }
    if (lane == 31) wS[wid] = x;
    __syncthreads();
    int woff = 0;
    #pragma unroll
    for (int k = 0; k < 8; k++)
        if (k < wid) woff += wS[k];
    int run = boff + woff + x - s;
    int4* bp = (int4*)g_base;
    #pragma unroll
    for (int j2 = 0; j2 < 4; j2++) {
        if (i4 + j2 < n4) {
            int4 o;
            o.x = run; run += v[j2].x;
            o.y = run; run += v[j2].y;
            o.z = run; run += v[j2].z;
            o.w = run; run += v[j2].w;
            bp[i4 + j2] = o;
        }
    }
}

// ================= K4: place || norm (norm 4x ILP, coalesced) ================
__global__ __launch_bounds__(256) void k4_kernel(
    const int* __restrict__ src, const int* __restrict__ dst,
    const float* __restrict__ ew, int E,
    const float4* __restrict__ x, const int* __restrict__ bmap, int total4,
    int nbP)
{
    int b = blockIdx.x, tid = threadIdx.x;
    if (b < nbP) {
        int i4 = b * 256 + tid;
        int e = i4 * 4;
        if (e + 3 < E) {
            int4 sv = __ldg((const int4*)src + i4);
            int4 dv = __ldg((const int4*)dst + i4);
            float4 wv = __ldg((const float4*)ew + i4);
            int p;
            p = g_base[dv.x] + atomicAdd(&g_cur[dv.x], 1);
            g_elist[p] = make_int2(sv.x, __float_as_int(wv.x));
            p = g_base[dv.y] + atomicAdd(&g_cur[dv.y], 1);
            g_elist[p] = make_int2(sv.y, __float_as_int(wv.y));
            p = g_base[dv.z] + atomicAdd(&g_cur[dv.z], 1);
            g_elist[p] = make_int2(sv.z, __float_as_int(wv.z));
            p = g_base[dv.w] + atomicAdd(&g_cur[dv.w], 1);
            g_elist[p] = make_int2(sv.w, __float_as_int(wv.w));
        } else {
            for (int j2 = 0; j2 < 4; j2++) {
                int ee = e + j2;
                if (ee < E) {
                    int d = __ldg(dst + ee);
                    int p = g_base[d] + atomicAdd(&g_cur[d], 1);
                    g_elist[p] = make_int2(__ldg(src + ee),
                                           __float_as_int(__ldg(ew + ee)));
                }
            }
        }
    } else {
        // norm: 4 block-strided float4s per thread — each load coalesced,
        // all 4 issued back-to-back (MLP 4)
        int tbase = (b - nbP) * 1024 + tid;
        float4 xv[4];
        #pragma unroll
        for (int k = 0; k < 4; k++) {
            int idx = tbase + k * 256;
            if (idx < total4) xv[k] = __ldg(x + idx);
        }
        #pragma unroll
        for (int k = 0; k < 4; k++) {
            int idx = tbase + k * 256;
            if (idx >= total4) continue;
            int r = idx >> 5, c = idx & 31;
            int g = __ldg(bmap + r);
            float4 a = ((const float4*)g_alpha)[g * 32 + c];
            float4 bb = ((const float4*)g_beta)[g * 32 + c];
            float ox = fmaf(a.x, xv[k].x, bb.x);
            float oy = fmaf(a.y, xv[k].y, bb.y);
            float oz = fmaf(a.z, xv[k].z, bb.z);
            float ow = fmaf(a.w, xv[k].w, bb.w);
            uint2 o;
            *(__half2*)&o.x = __floats2half2_rn(ox, oy);
            *(__half2*)&o.y = __floats2half2_rn(oz, ow);
            ((uint2*)g_xnh)[idx] = o;
        }
    }
}

// ---------------- gather: half-warp per row, uint4 loads, 4-edge ILP ---------
__device__ __forceinline__ void gacc(float* acc, uint4 v, float w) {
    float2 p0 = __half22float2(*(__half2*)&v.x);
    float2 p1 = __half22float2(*(__half2*)&v.y);
    float2 p2 = __half22float2(*(__half2*)&v.z);
    float2 p3 = __half22float2(*(__half2*)&v.w);
    acc[0] = fmaf(w, p0.x, acc[0]); acc[1] = fmaf(w, p0.y, acc[1]);
    acc[2] = fmaf(w, p1.x, acc[2]); acc[3] = fmaf(w, p1.y, acc[3]);
    acc[4] = fmaf(w, p2.x, acc[4]); acc[5] = fmaf(w, p2.y, acc[5]);
    acc[6] = fmaf(w, p3.x, acc[6]); acc[7] = fmaf(w, p3.y, acc[7]);
}

__global__ __launch_bounds__(256) void gather_kernel(
    const uint4* __restrict__ in, uint4* __restrict__ agg, int n)
{
    int row = (blockIdx.x * 256 + threadIdx.x) >> 4;   // one half-warp per row
    if (row >= n) return;
    int c = threadIdx.x & 15;
    int b0 = g_base[row], b1 = g_base[row + 1];
    if (c == 0) g_cur[row] = 0;                        // self-clean for replay
    float acc[8];
    #pragma unroll
    for (int i = 0; i < 8; i++) acc[i] = 0.f;
    int e = b0;
    #pragma unroll 1
    for (; e + 4 <= b1; e += 4) {
        int2 s0 = __ldg(&g_elist[e]);
        int2 s1 = __ldg(&g_elist[e + 1]);
        int2 s2 = __ldg(&g_elist[e + 2]);
        int2 s3 = __ldg(&g_elist[e + 3]);
        uint4 v0 = __ldg(in + (size_t)s0.x * 16 + c);
        uint4 v1 = __ldg(in + (size_t)s1.x * 16 + c);
        uint4 v2 = __ldg(in + (size_t)s2.x * 16 + c);
        uint4 v3 = __ldg(in + (size_t)s3.x * 16 + c);
        gacc(acc, v0, __int_as_float(s0.y));
        gacc(acc, v1, __int_as_float(s1.y));
        gacc(acc, v2, __int_as_float(s2.y));
        gacc(acc, v3, __int_as_float(s3.y));
    }
    #pragma unroll 1
    for (; e < b1; e++) {
        int2 s0 = __ldg(&g_elist[e]);
        uint4 v0 = __ldg(in + (size_t)s0.x * 16 + c);
        gacc(acc, v0, __int_as_float(s0.y));
    }
    uint4 o;
    *(__half2*)&o.x = __floats2half2_rn(acc[0], acc[1]);
    *(__half2*)&o.y = __floats2half2_rn(acc[2], acc[3]);
    *(__half2*)&o.z = __floats2half2_rn(acc[4], acc[5]);
    *(__half2*)&o.w = __floats2half2_rn(acc[6], acc[7]);
    agg[(size_t)row * 16 + c] = o;
}

// ---------------- fp16 warp-MMA GEMM, cp.async pipelined (round-9 config) ----
#define GB_A0   1024
#define GB_W    (GB_A0 + 3 * 16384)
#define GB_SMEM (GB_W + 65536)

__device__ __forceinline__ void cpA(uint32_t sbase, int buf, int tid, int r0,
                                    int n, int c,
                                    const __half* __restrict__ Arel,
                                    const __half* __restrict__ Aroot)
{
    const char* As = (const char*)((c < 2) ? Arel : Aroot);
    int off = (c & 1) * 128;
    #pragma unroll
    for (int i = 0; i < 4; i++) {
        int q = tid + i * 256;
        int row = q >> 3, u = q & 7;
        int gr = r0 + row;
        cp16(sbase + GB_A0 + buf * 16384 + row * 128 + (((u ^ (row & 7)) & 7) << 4),
             As + (size_t)gr * 256 + off + u * 16, gr < n);
    }
}

template <int MODE>
__global__ __launch_bounds__(256) void gemm_h_kernel(
    const __half* __restrict__ Arel, const __half* __restrict__ Aroot,
    const __half* __restrict__ wh, const float* __restrict__ brel,
    const float* __restrict__ resid, void* __restrict__ outv, int n)
{
    extern __shared__ char smem[];
    uint32_t sbase = smem_u32(smem);
    int tid = threadIdx.x, wid = tid >> 5, lane = tid & 31;
    int wm = wid & 3, wn = wid >> 2;
    int r0 = blockIdx.x * 128;

    if (tid < 128) ((float*)smem)[tid] = __ldg(brel + tid);

    #pragma unroll
    for (int i = 0; i < 16; i++) {
        int q = tid + i * 256;
        int row = q >> 5, uu = q & 31;
        int phys = (uu & 0x18) | ((uu ^ row) & 7);
        cp16(sbase + GB_W + row * 512 + phys * 16,
             (const char*)wh + (size_t)row * 512 + uu * 16, true);
    }
    cpA(sbase, 0, tid, r0, n, 0, Arel, Aroot);
    CP_COMMIT();
    cpA(sbase, 1, tid, r0, n, 1, Arel, Aroot);
    CP_COMMIT();

    float acc[2][8][4];
    #pragma unroll
    for (int t = 0; t < 2; t++)
        #pragma unroll
        for (int u = 0; u < 8; u++)
            #pragma unroll
            for (int v = 0; v < 4; v++) acc[t][u][v] = 0.f;

    int j = lane & 7, grp = lane >> 3;
    int a_row = wm * 32 + ((grp & 1) << 3) + j;
    int a_ub  = grp >> 1;
    int b_row = wn * 64 + (((grp >> 1) & 1) << 3) + j;
    int b_r7  = b_row & 7;
    int b_ub  = grp & 1;

    #pragma unroll 1
    for (int c = 0; c < 4; c++) {
        if (c < 3) { CP_WAIT(1); } else { CP_WAIT(0); }
        __syncthreads();
        if (c < 2) {
            cpA(sbase, (c + 2) % 3, tid, r0, n, c + 2, Arel, Aroot);
            CP_COMMIT();
        }
        uint32_t aB = sbase + GB_A0 + (uint32_t)(c % 3) * 16384;
        #pragma unroll
        for (int ks = 0; ks < 4; ks++) {
            uint4 af[2];
            #pragma unroll
            for (int t = 0; t < 2; t++) {
                int row = a_row + t * 16;
                int u = ks * 2 + a_ub;
                ldsm4(af[t], aB + row * 128 + (((u ^ (row & 7)) & 7) << 4));
            }
            uint4 bf[4];
            #pragma unroll
            for (int p = 0; p < 4; p++) {
                int row = b_row + p * 16;
                int uu = c * 8 + ks * 2 + b_ub;
                int phys = (uu & 0x18) | ((uu ^ b_r7) & 7);
                ldsm4(bf[p], sbase + GB_W + row * 512 + phys * 16);
            }
            #pragma unroll
            for (int t = 0; t < 2; t++)
                #pragma unroll
                for (int u = 0; u < 8; u++) {
                    int p = u >> 1;
                    uint32_t b0 = (u & 1) ? bf[p].z : bf[p].x;
                    uint32_t b1 = (u & 1) ? bf[p].w : bf[p].y;
                    mma16816(acc[t][u], af[t], b0, b1);
                }
        }
    }

    const float* bias = (const float*)smem;
    int rb = r0 + wm * 32 + (lane >> 2);
    int cb = wn * 64 + ((lane & 3) << 1);
    #pragma unroll
    for (int t = 0; t < 2; t++) {
        #pragma unroll
        for (int u = 0; u < 8; u++) {
            int cc = cb + u * 8;
            float b0v = bias[cc], b1v = bias[cc + 1];
            #pragma unroll
            for (int h = 0; h < 2; h++) {
                int r = rb + t * 16 + h * 8;
                if (r >= n) continue;
                float vx = acc[t][u][h * 2 + 0] + b0v;
                float vy = acc[t][u][h * 2 + 1] + b1v;
                if (MODE == 0) {
                    vx = (vx >= 0.f) ? vx : 0.1f * vx;
                    vy = (vy >= 0.f) ? vy : 0.1f * vy;
                    __half2* op = (__half2*)((__half*)outv + (size_t)r * W + cc);
                    *op = __floats2half2_rn(vx, vy);
                } else {
                    float2 rr = *(const float2*)(resid + (size_t)r * W + cc);
                    vx += rr.x; vy += rr.y;
                    *(float2*)((float*)outv + (size_t)r * W + cc) =
                        make_float2(vx, vy);
                }
            }
        }
    }
}

// ---------------- launch -----------------------------------------------------
extern "C" void kernel_launch(void* const* d_in, const int* in_sizes, int n_in,
                              void* d_out, int out_size)
{
    const float* x      = (const float*)d_in[0];
    const int*   eidx   = (const int*)d_in[1];
    const float* ew     = (const float*)d_in[2];
    const int*   bmap   = (const int*)d_in[3];
    const float* gnw    = (const float*)d_in[4];
    const float* gnb    = (const float*)d_in[5];
    const float* msc    = (const float*)d_in[6];
    const float* Wrel1  = (const float*)d_in[7];
    const float* brel1  = (const float*)d_in[8];
    const float* Wroot1 = (const float*)d_in[9];
    const float* Wrel2  = (const float*)d_in[10];
    const float* brel2  = (const float*)d_in[11];
    const float* Wroot2 = (const float*)d_in[12];
    float* out = (float*)d_out;

    int n = in_sizes[0] / W;
    int E = in_sizes[2];
    const int* src = eidx;
    const int* dst = eidx + E;

    void *p_xnh, *p_aggh, *p_h1h, *p_wh;
    cudaGetSymbolAddress(&p_xnh, g_xnh);
    cudaGetSymbolAddress(&p_aggh, g_aggh);
    cudaGetSymbolAddress(&p_h1h, g_h1h);
    cudaGetSymbolAddress(&p_wh, g_wh);
    __half* xnh  = (__half*)p_xnh;
    __half* aggh = (__half*)p_aggh;
    __half* h1h  = (__half*)p_h1h;
    __half* wh   = (__half*)p_wh;

    cudaFuncSetAttribute(gemm_h_kernel<0>,
                         cudaFuncAttributeMaxDynamicSharedMemorySize, GB_SMEM);
    cudaFuncSetAttribute(gemm_h_kernel<1>,
                         cudaFuncAttributeMaxDynamicSharedMemorySize, GB_SMEM);

    // K1: stats || hist || wprep
    int nbS = (n + 255) / 256;
    int nbH = (E + 1023) / 1024;
    int nbW = 128;
    k1_kernel<<<nbS + nbH + nbW, 256>>>(x, bmap, n, dst, E,
                                        Wrel1, Wroot1, Wrel2, Wroot2, nbS, nbH);

    // K2: finalize || scan1
    int n4 = (n + 3) / 4;
    int nscan = (n4 + 1023) / 1024;
    int nbF = (G * W) / 256;
    k2_kernel<<<nbF + nscan, 256>>>(gnw, gnb, msc, n4, nbF);

    // K3: scan3 (inline scan2)
    k3_kernel<<<nscan, 256>>>(n4, nscan, n);

    // K4: place || norm (norm 4x ILP, coalesced)
    int nbP = (E + 1023) / 1024;
    int total4 = n * 32;
    int nbN = (total4 + 1023) / 1024;
    k4_kernel<<<nbP + nbN, 256>>>(src, dst, ew, E,
                                  (const float4*)x, bmap, total4, nbP);

    // conv1: gather + GEMM(+LeakyReLU) -> fp16 h1
    int gwBlocks = (n * 16 + 255) / 256;
    gather_kernel<<<gwBlocks, 256>>>((const uint4*)xnh, (uint4*)aggh, n);
    int gBlocks = (n + 127) / 128;
    gemm_h_kernel<0><<<gBlocks, 256, GB_SMEM>>>(
        aggh, xnh, wh, brel1, nullptr, h1h, n);

    // conv2: gather + GEMM(+residual) -> fp32 out
    gather_kernel<<<gwBlocks, 256>>>((const uint4*)h1h, (uint4*)aggh, n);
    gemm_h_kernel<1><<<gBlocks, 256, GB_SMEM>>>(
        aggh, h1h, wh + 128 * 256, brel2, x, out, n);
}

// round 16
// speedup vs baseline: 1.4400x; 1.0390x over previous
#include <cuda_runtime.h>
#include <cuda_fp16.h>
#include <cstdint>

#define W 128
#define G 64
#define MAXN 100000
#define MAXE 625000
#define EPS 1e-5f

// ---------------- scratch (static device globals; zero-initialized) ----------
__device__ __half g_xnh[MAXN * W];
__device__ __half g_aggh[MAXN * W];
__device__ __half g_h1h[MAXN * W];
__device__ __half g_wh[2 * 128 * 256];
__device__ float g_sum[G * W];        // self-cleaned by finalize
__device__ float g_sumsq[G * W];      // self-cleaned by finalize
__device__ float g_cnt[G];            // self-cleaned by finalize
__device__ float g_alpha[G * W];
__device__ float g_beta[G * W];
__device__ int   g_deg[MAXN];         // self-cleaned by scan3
__device__ int   g_base[MAXN + 4];
__device__ int   g_cur[MAXN];         // self-cleaned by gather
__device__ int2  g_elist[MAXE];
__device__ int   g_bsum[64];

// ---------------- PTX helpers (sm_80/90 baseline only) -----------------------
__device__ __forceinline__ uint32_t smem_u32(const void* p) {
    uint32_t a;
    asm("{ .reg .u64 t; cvta.to.shared.u64 t, %1; cvt.u32.u64 %0, t; }"
        : "=r"(a) : "l"(p));
    return a;
}
__device__ __forceinline__ void ldsm4(uint4& r, uint32_t addr) {
    asm volatile("ldmatrix.sync.aligned.m8n8.x4.shared.b16 {%0,%1,%2,%3}, [%4];"
                 : "=r"(r.x), "=r"(r.y), "=r"(r.z), "=r"(r.w) : "r"(addr));
}
__device__ __forceinline__ void mma16816(float* d, const uint4& a,
                                         uint32_t b0, uint32_t b1) {
    asm volatile(
        "mma.sync.aligned.m16n8k16.row.col.f32.f16.f16.f32 "
        "{%0,%1,%2,%3}, {%4,%5,%6,%7}, {%8,%9}, {%0,%1,%2,%3};"
        : "+f"(d[0]), "+f"(d[1]), "+f"(d[2]), "+f"(d[3])
        : "r"(a.x), "r"(a.y), "r"(a.z), "r"(a.w), "r"(b0), "r"(b1));
}
__device__ __forceinline__ void cp16(uint32_t dst, const void* src, bool pred) {
    int sz = pred ? 16 : 0;
    asm volatile("cp.async.cg.shared.global [%0], [%1], 16, %2;"
                 :: "r"(dst), "l"(src), "r"(sz) : "memory");
}
#define CP_COMMIT() asm volatile("cp.async.commit_group;" ::: "memory")
#define CP_WAIT(N)  asm volatile("cp.async.wait_group %0;" :: "n"(N) : "memory")

// ================= K1: stats || hist || wprep (grid-partitioned) =============
__global__ __launch_bounds__(256) void k1_kernel(
    const float* __restrict__ x, const int* __restrict__ bmap, int n,
    const int* __restrict__ dst, int E,
    const float* __restrict__ Wr1, const float* __restrict__ Wo1,
    const float* __restrict__ Wr2, const float* __restrict__ Wo2,
    int nbS, int nbH)
{
    int b = blockIdx.x, tid = threadIdx.x;
    if (b < nbS) {
        int f = tid & 127, sub = tid >> 7;
        int n0 = b * 256 + sub * 128;
        if (n0 >= n) return;
        int n1 = min(n0 + 128, n);
        float s = 0.f, ss = 0.f;
        int curg = __ldg(bmap + n0);
        int r = n0;
        // 8-row unrolled: loads issued before group checks (MLP 8)
        #pragma unroll 1
        for (; r + 8 <= n1; r += 8) {
            int gg[8];
            float vv[8];
            #pragma unroll
            for (int k = 0; k < 8; k++) gg[k] = __ldg(bmap + r + k);
            #pragma unroll
            for (int k = 0; k < 8; k++) vv[k] = x[(size_t)(r + k) * W + f];
            #pragma unroll
            for (int k = 0; k < 8; k++) {
                if (gg[k] != curg) {
                    atomicAdd(&g_sum[curg * W + f], s);
                    atomicAdd(&g_sumsq[curg * W + f], ss);
                    s = 0.f; ss = 0.f; curg = gg[k];
                }
                s += vv[k]; ss += vv[k] * vv[k];
            }
        }
        #pragma unroll 1
        for (; r < n1; r++) {
            int g = __ldg(bmap + r);
            if (g != curg) {
                atomicAdd(&g_sum[curg * W + f], s);
                atomicAdd(&g_sumsq[curg * W + f], ss);
                s = 0.f; ss = 0.f; curg = g;
            }
            float v = x[(size_t)r * W + f];
            s += v; ss += v * v;
        }
        atomicAdd(&g_sum[curg * W + f], s);
        atomicAdd(&g_sumsq[curg * W + f], ss);
        if (f == 0) {
            int cg = __ldg(bmap + n0), rs = n0;
            for (int rr = n0; rr < n1; rr++) {
                int g = __ldg(bmap + rr);
                if (g != cg) {
                    atomicAdd(&g_cnt[cg], (float)(rr - rs));
                    cg = g; rs = rr;
                }
            }
            atomicAdd(&g_cnt[cg], (float)(n1 - rs));
        }
    } else if (b < nbS + nbH) {
        int i4 = (b - nbS) * 256 + tid;
        int e = i4 * 4;
        if (e + 3 < E) {
            int4 d = __ldg((const int4*)dst + i4);
            atomicAdd(&g_deg[d.x], 1);
            atomicAdd(&g_deg[d.y], 1);
            atomicAdd(&g_deg[d.z], 1);
            atomicAdd(&g_deg[d.w], 1);
        } else {
            for (int j2 = 0; j2 < 4; j2++)
                if (e + j2 < E) atomicAdd(&g_deg[__ldg(dst + e + j2)], 1);
        }
    } else {
        int idx = (b - nbS - nbH) * 256 + tid;
        int conv = idx >> 14;
        int rem  = idx & 16383;
        int row  = rem >> 7;
        int c2   = rem & 127;
        const float* Wr = conv ? Wr2 : Wr1;
        const float* Wo = conv ? Wo2 : Wo1;
        const float* s = (c2 < 64) ? (Wr + row * 128 + c2 * 2)
                                   : (Wo + row * 128 + (c2 - 64) * 2);
        float2 v = *(const float2*)s;
        ((__half2*)(g_wh + (size_t)conv * 128 * 256 + row * 256))[c2] =
            __floats2half2_rn(v.x, v.y);
    }
}

// ================= K2: finalize || scan1 =====================================
__global__ __launch_bounds__(256) void k2_kernel(
    const float* __restrict__ gnw, const float* __restrict__ gnb,
    const float* __restrict__ msc, int n4, int nbF)
{
    int b = blockIdx.x, tid = threadIdx.x, lane = tid & 31, wid = tid >> 5;
    if (b < nbF) {
        int idx = b * 256 + tid;
        int g = idx >> 7, f = idx & 127;
        float cnt  = g_cnt[g];
        float inv  = (cnt > 0.f) ? (1.f / cnt) : 0.f;
        float mean = g_sum[idx] * inv;
        float q    = g_sumsq[idx] * inv;
        g_sum[idx] = 0.f;
        g_sumsq[idx] = 0.f;
        float m    = __ldg(msc + f);
        float var  = q - mean * mean * m * (2.f - m);
        float istd = rsqrtf(var + EPS);
        float a    = __ldg(gnw + f) * istd;
        g_alpha[idx] = a;
        g_beta[idx]  = __ldg(gnb + f) - a * m * mean;
        __syncthreads();
        if (f == 0) g_cnt[g] = 0.f;
    } else {
        __shared__ int wS[8];
        int sb = b - nbF;
        const int4* dp = (const int4*)g_deg;
        int i4 = sb * 1024 + tid * 4;
        int s = 0;
        #pragma unroll
        for (int j2 = 0; j2 < 4; j2++) {
            if (i4 + j2 < n4) {
                int4 v = dp[i4 + j2];
                s += v.x + v.y + v.z + v.w;
            }
        }
        #pragma unroll
        for (int o = 16; o > 0; o >>= 1) s += __shfl_down_sync(~0u, s, o);
        if (lane == 0) wS[wid] = s;
        __syncthreads();
        if (tid == 0) {
            int t = 0;
            #pragma unroll
            for (int k = 0; k < 8; k++) t += wS[k];
            g_bsum[sb] = t;
        }
    }
}

// ================= K3: scan3 (with inline scan2 over g_bsum) =================
__global__ __launch_bounds__(256) void k3_kernel(int n4, int nscan, int n)
{
    __shared__ int wS[8];
    __shared__ int boff;
    int b = blockIdx.x, tid = threadIdx.x, lane = tid & 31, wid = tid >> 5;
    if (tid == 0) {
        int run = 0;
        for (int i = 0; i < b; i++) run += g_bsum[i];
        boff = run;
        if (b == 0) {
            int tot = 0;
            for (int i = 0; i < nscan; i++) tot += g_bsum[i];
            g_base[n] = tot;
        }
    }
    int4* dp = (int4*)g_deg;
    int i4 = b * 1024 + tid * 4;
    int4 v[4];
    int s = 0;
    #pragma unroll
    for (int j2 = 0; j2 < 4; j2++) {
        v[j2] = make_int4(0, 0, 0, 0);
        if (i4 + j2 < n4) {
            v[j2] = dp[i4 + j2];
            dp[i4 + j2] = make_int4(0, 0, 0, 0);
        }
        s += v[j2].x + v[j2].y + v[j2].z + v[j2].w;
    }
    int x = s;
    #pragma unroll
    for (int o = 1; o < 32; o <<= 1) {
        int y = __shfl_up_sync(~0u, x, o);
        if (lane >= o) x += y;
    }
    if (lane == 31) wS[wid] = x;
    __syncthreads();
    int woff = 0;
    #pragma unroll
    for (int k = 0; k < 8; k++)
        if (k < wid) woff += wS[k];
    int run = boff + woff + x - s;
    int4* bp = (int4*)g_base;
    #pragma unroll
    for (int j2 = 0; j2 < 4; j2++) {
        if (i4 + j2 < n4) {
            int4 o;
            o.x = run; run += v[j2].x;
            o.y = run; run += v[j2].y;
            o.z = run; run += v[j2].z;
            o.w = run; run += v[j2].w;
            bp[i4 + j2] = o;
        }
    }
}

// ================= K4: place || norm (norm 8x ILP, coalesced) ================
__global__ __launch_bounds__(256) void k4_kernel(
    const int* __restrict__ src, const int* __restrict__ dst,
    const float* __restrict__ ew, int E,
    const float4* __restrict__ x, const int* __restrict__ bmap, int total4,
    int nbP)
{
    int b = blockIdx.x, tid = threadIdx.x;
    if (b < nbP) {
        int i4 = b * 256 + tid;
        int e = i4 * 4;
        if (e + 3 < E) {
            int4 sv = __ldg((const int4*)src + i4);
            int4 dv = __ldg((const int4*)dst + i4);
            float4 wv = __ldg((const float4*)ew + i4);
            int p;
            p = g_base[dv.x] + atomicAdd(&g_cur[dv.x], 1);
            g_elist[p] = make_int2(sv.x, __float_as_int(wv.x));
            p = g_base[dv.y] + atomicAdd(&g_cur[dv.y], 1);
            g_elist[p] = make_int2(sv.y, __float_as_int(wv.y));
            p = g_base[dv.z] + atomicAdd(&g_cur[dv.z], 1);
            g_elist[p] = make_int2(sv.z, __float_as_int(wv.z));
            p = g_base[dv.w] + atomicAdd(&g_cur[dv.w], 1);
            g_elist[p] = make_int2(sv.w, __float_as_int(wv.w));
        } else {
            for (int j2 = 0; j2 < 4; j2++) {
                int ee = e + j2;
                if (ee < E) {
                    int d = __ldg(dst + ee);
                    int p = g_base[d] + atomicAdd(&g_cur[d], 1);
                    g_elist[p] = make_int2(__ldg(src + ee),
                                           __float_as_int(__ldg(ew + ee)));
                }
            }
        }
    } else {
        // norm: 8 block-strided float4s per thread — each load coalesced,
        // all 8 issued back-to-back (MLP 8)
        int tbase = (b - nbP) * 2048 + tid;
        float4 xv[8];
        #pragma unroll
        for (int k = 0; k < 8; k++) {
            int idx = tbase + k * 256;
            if (idx < total4) xv[k] = __ldg(x + idx);
        }
        #pragma unroll
        for (int k = 0; k < 8; k++) {
            int idx = tbase + k * 256;
            if (idx >= total4) continue;
            int r = idx >> 5, c = idx & 31;
            int g = __ldg(bmap + r);
            float4 a = ((const float4*)g_alpha)[g * 32 + c];
            float4 bb = ((const float4*)g_beta)[g * 32 + c];
            float ox = fmaf(a.x, xv[k].x, bb.x);
            float oy = fmaf(a.y, xv[k].y, bb.y);
            float oz = fmaf(a.z, xv[k].z, bb.z);
            float ow = fmaf(a.w, xv[k].w, bb.w);
            uint2 o;
            *(__half2*)&o.x = __floats2half2_rn(ox, oy);
            *(__half2*)&o.y = __floats2half2_rn(oz, ow);
            ((uint2*)g_xnh)[idx] = o;
        }
    }
}

// ---------------- gather: half-warp per row, uint4 loads, 4/2/1-edge ILP -----
__device__ __forceinline__ void gacc(float* acc, uint4 v, float w) {
    float2 p0 = __half22float2(*(__half2*)&v.x);
    float2 p1 = __half22float2(*(__half2*)&v.y);
    float2 p2 = __half22float2(*(__half2*)&v.z);
    float2 p3 = __half22float2(*(__half2*)&v.w);
    acc[0] = fmaf(w, p0.x, acc[0]); acc[1] = fmaf(w, p0.y, acc[1]);
    acc[2] = fmaf(w, p1.x, acc[2]); acc[3] = fmaf(w, p1.y, acc[3]);
    acc[4] = fmaf(w, p2.x, acc[4]); acc[5] = fmaf(w, p2.y, acc[5]);
    acc[6] = fmaf(w, p3.x, acc[6]); acc[7] = fmaf(w, p3.y, acc[7]);
}

__global__ __launch_bounds__(256) void gather_kernel(
    const uint4* __restrict__ in, uint4* __restrict__ agg, int n)
{
    int row = (blockIdx.x * 256 + threadIdx.x) >> 4;   // one half-warp per row
    if (row >= n) return;
    int c = threadIdx.x & 15;
    int b0 = g_base[row], b1 = g_base[row + 1];
    if (c == 0) g_cur[row] = 0;                        // self-clean for replay
    float acc[8];
    #pragma unroll
    for (int i = 0; i < 8; i++) acc[i] = 0.f;
    int e = b0;
    #pragma unroll 1
    for (; e + 4 <= b1; e += 4) {
        int2 s0 = __ldg(&g_elist[e]);
        int2 s1 = __ldg(&g_elist[e + 1]);
        int2 s2 = __ldg(&g_elist[e + 2]);
        int2 s3 = __ldg(&g_elist[e + 3]);
        uint4 v0 = __ldg(in + (size_t)s0.x * 16 + c);
        uint4 v1 = __ldg(in + (size_t)s1.x * 16 + c);
        uint4 v2 = __ldg(in + (size_t)s2.x * 16 + c);
        uint4 v3 = __ldg(in + (size_t)s3.x * 16 + c);
        gacc(acc, v0, __int_as_float(s0.y));
        gacc(acc, v1, __int_as_float(s1.y));
        gacc(acc, v2, __int_as_float(s2.y));
        gacc(acc, v3, __int_as_float(s3.y));
    }
    if (e + 2 <= b1) {
        int2 s0 = __ldg(&g_elist[e]);
        int2 s1 = __ldg(&g_elist[e + 1]);
        uint4 v0 = __ldg(in + (size_t)s0.x * 16 + c);
        uint4 v1 = __ldg(in + (size_t)s1.x * 16 + c);
        gacc(acc, v0, __int_as_float(s0.y));
        gacc(acc, v1, __int_as_float(s1.y));
        e += 2;
    }
    if (e < b1) {
        int2 s0 = __ldg(&g_elist[e]);
        uint4 v0 = __ldg(in + (size_t)s0.x * 16 + c);
        gacc(acc, v0, __int_as_float(s0.y));
    }
    uint4 o;
    *(__half2*)&o.x = __floats2half2_rn(acc[0], acc[1]);
    *(__half2*)&o.y = __floats2half2_rn(acc[2], acc[3]);
    *(__half2*)&o.z = __floats2half2_rn(acc[4], acc[5]);
    *(__half2*)&o.w = __floats2half2_rn(acc[6], acc[7]);
    agg[(size_t)row * 16 + c] = o;
}

// ---------------- fp16 warp-MMA GEMM, cp.async pipelined (round-9 config) ----
#define GB_A0   1024
#define GB_W    (GB_A0 + 3 * 16384)
#define GB_SMEM (GB_W + 65536)

__device__ __forceinline__ void cpA(uint32_t sbase, int buf, int tid, int r0,
                                    int n, int c,
                                    const __half* __restrict__ Arel,
                                    const __half* __restrict__ Aroot)
{
    const char* As = (const char*)((c < 2) ? Arel : Aroot);
    int off = (c & 1) * 128;
    #pragma unroll
    for (int i = 0; i < 4; i++) {
        int q = tid + i * 256;
        int row = q >> 3, u = q & 7;
        int gr = r0 + row;
        cp16(sbase + GB_A0 + buf * 16384 + row * 128 + (((u ^ (row & 7)) & 7) << 4),
             As + (size_t)gr * 256 + off + u * 16, gr < n);
    }
}

template <int MODE>
__global__ __launch_bounds__(256) void gemm_h_kernel(
    const __half* __restrict__ Arel, const __half* __restrict__ Aroot,
    const __half* __restrict__ wh, const float* __restrict__ brel,
    const float* __restrict__ resid, void* __restrict__ outv, int n)
{
    extern __shared__ char smem[];
    uint32_t sbase = smem_u32(smem);
    int tid = threadIdx.x, wid = tid >> 5, lane = tid & 31;
    int wm = wid & 3, wn = wid >> 2;
    int r0 = blockIdx.x * 128;

    if (tid < 128) ((float*)smem)[tid] = __ldg(brel + tid);

    #pragma unroll
    for (int i = 0; i < 16; i++) {
        int q = tid + i * 256;
        int row = q >> 5, uu = q & 31;
        int phys = (uu & 0x18) | ((uu ^ row) & 7);
        cp16(sbase + GB_W + row * 512 + phys * 16,
             (const char*)wh + (size_t)row * 512 + uu * 16, true);
    }
    cpA(sbase, 0, tid, r0, n, 0, Arel, Aroot);
    CP_COMMIT();
    cpA(sbase, 1, tid, r0, n, 1, Arel, Aroot);
    CP_COMMIT();

    float acc[2][8][4];
    #pragma unroll
    for (int t = 0; t < 2; t++)
        #pragma unroll
        for (int u = 0; u < 8; u++)
            #pragma unroll
            for (int v = 0; v < 4; v++) acc[t][u][v] = 0.f;

    int j = lane & 7, grp = lane >> 3;
    int a_row = wm * 32 + ((grp & 1) << 3) + j;
    int a_ub  = grp >> 1;
    int b_row = wn * 64 + (((grp >> 1) & 1) << 3) + j;
    int b_r7  = b_row & 7;
    int b_ub  = grp & 1;

    #pragma unroll 1
    for (int c = 0; c < 4; c++) {
        if (c < 3) { CP_WAIT(1); } else { CP_WAIT(0); }
        __syncthreads();
        if (c < 2) {
            cpA(sbase, (c + 2) % 3, tid, r0, n, c + 2, Arel, Aroot);
            CP_COMMIT();
        }
        uint32_t aB = sbase + GB_A0 + (uint32_t)(c % 3) * 16384;
        #pragma unroll
        for (int ks = 0; ks < 4; ks++) {
            uint4 af[2];
            #pragma unroll
            for (int t = 0; t < 2; t++) {
                int row = a_row + t * 16;
                int u = ks * 2 + a_ub;
                ldsm4(af[t], aB + row * 128 + (((u ^ (row & 7)) & 7) << 4));
            }
            uint4 bf[4];
            #pragma unroll
            for (int p = 0; p < 4; p++) {
                int row = b_row + p * 16;
                int uu = c * 8 + ks * 2 + b_ub;
                int phys = (uu & 0x18) | ((uu ^ b_r7) & 7);
                ldsm4(bf[p], sbase + GB_W + row * 512 + phys * 16);
            }
            #pragma unroll
            for (int t = 0; t < 2; t++)
                #pragma unroll
                for (int u = 0; u < 8; u++) {
                    int p = u >> 1;
                    uint32_t b0 = (u & 1) ? bf[p].z : bf[p].x;
                    uint32_t b1 = (u & 1) ? bf[p].w : bf[p].y;
                    mma16816(acc[t][u], af[t], b0, b1);
                }
        }
    }

    const float* bias = (const float*)smem;
    int rb = r0 + wm * 32 + (lane >> 2);
    int cb = wn * 64 + ((lane & 3) << 1);
    #pragma unroll
    for (int t = 0; t < 2; t++) {
        #pragma unroll
        for (int u = 0; u < 8; u++) {
            int cc = cb + u * 8;
            float b0v = bias[cc], b1v = bias[cc + 1];
            #pragma unroll
            for (int h = 0; h < 2; h++) {
                int r = rb + t * 16 + h * 8;
                if (r >= n) continue;
                float vx = acc[t][u][h * 2 + 0] + b0v;
                float vy = acc[t][u][h * 2 + 1] + b1v;
                if (MODE == 0) {
                    vx = (vx >= 0.f) ? vx : 0.1f * vx;
                    vy = (vy >= 0.f) ? vy : 0.1f * vy;
                    __half2* op = (__half2*)((__half*)outv + (size_t)r * W + cc);
                    *op = __floats2half2_rn(vx, vy);
                } else {
                    float2 rr = *(const float2*)(resid + (size_t)r * W + cc);
                    vx += rr.x; vy += rr.y;
                    *(float2*)((float*)outv + (size_t)r * W + cc) =
                        make_float2(vx, vy);
                }
            }
        }
    }
}

// ---------------- launch -----------------------------------------------------
extern "C" void kernel_launch(void* const* d_in, const int* in_sizes, int n_in,
                              void* d_out, int out_size)
{
    const float* x      = (const float*)d_in[0];
    const int*   eidx   = (const int*)d_in[1];
    const float* ew     = (const float*)d_in[2];
    const int*   bmap   = (const int*)d_in[3];
    const float* gnw    = (const float*)d_in[4];
    const float* gnb    = (const float*)d_in[5];
    const float* msc    = (const float*)d_in[6];
    const float* Wrel1  = (const float*)d_in[7];
    const float* brel1  = (const float*)d_in[8];
    const float* Wroot1 = (const float*)d_in[9];
    const float* Wrel2  = (const float*)d_in[10];
    const float* brel2  = (const float*)d_in[11];
    const float* Wroot2 = (const float*)d_in[12];
    float* out = (float*)d_out;

    int n = in_sizes[0] / W;
    int E = in_sizes[2];
    const int* src = eidx;
    const int* dst = eidx + E;

    void *p_xnh, *p_aggh, *p_h1h, *p_wh;
    cudaGetSymbolAddress(&p_xnh, g_xnh);
    cudaGetSymbolAddress(&p_aggh, g_aggh);
    cudaGetSymbolAddress(&p_h1h, g_h1h);
    cudaGetSymbolAddress(&p_wh, g_wh);
    __half* xnh  = (__half*)p_xnh;
    __half* aggh = (__half*)p_aggh;
    __half* h1h  = (__half*)p_h1h;
    __half* wh   = (__half*)p_wh;

    cudaFuncSetAttribute(gemm_h_kernel<0>,
                         cudaFuncAttributeMaxDynamicSharedMemorySize, GB_SMEM);
    cudaFuncSetAttribute(gemm_h_kernel<1>,
                         cudaFuncAttributeMaxDynamicSharedMemorySize, GB_SMEM);

    // K1: stats || hist || wprep
    int nbS = (n + 255) / 256;
    int nbH = (E + 1023) / 1024;
    int nbW = 128;
    k1_kernel<<<nbS + nbH + nbW, 256>>>(x, bmap, n, dst, E,
                                        Wrel1, Wroot1, Wrel2, Wroot2, nbS, nbH);

    // K2: finalize || scan1
    int n4 = (n + 3) / 4;
    int nscan = (n4 + 1023) / 1024;
    int nbF = (G * W) / 256;
    k2_kernel<<<nbF + nscan, 256>>>(gnw, gnb, msc, n4, nbF);

    // K3: scan3 (inline scan2)
    k3_kernel<<<nscan, 256>>>(n4, nscan, n);

    // K4: place || norm (norm 8x ILP, coalesced)
    int nbP = (E + 1023) / 1024;
    int total4 = n * 32;
    int nbN = (total4 + 2047) / 2048;
    k4_kernel<<<nbP + nbN, 256>>>(src, dst, ew, E,
                                  (const float4*)x, bmap, total4, nbP);

    // conv1: gather + GEMM(+LeakyReLU) -> fp16 h1
    int gwBlocks = (n * 16 + 255) / 256;
    gather_kernel<<<gwBlocks, 256>>>((const uint4*)xnh, (uint4*)aggh, n);
    int gBlocks = (n + 127) / 128;
    gemm_h_kernel<0><<<gBlocks, 256, GB_SMEM>>>(
        aggh, xnh, wh, brel1, nullptr, h1h, n);

    // conv2: gather + GEMM(+residual) -> fp32 out
    gather_kernel<<<gwBlocks, 256>>>((const uint4*)h1h, (uint4*)aggh, n);
    gemm_h_kernel<1><<<gBlocks, 256, GB_SMEM>>>(
        aggh, h1h, wh + 128 * 256, brel2, x, out, n);
}

// round 17
// speedup vs baseline: 1.4535x; 1.0094x over previous
#include <cuda_runtime.h>
#include <cuda_fp16.h>
#include <cstdint>

#define W 128
#define G 64
#define MAXN 100000
#define MAXE 625000
#define EPS 1e-5f

// ---------------- scratch (static device globals; zero-initialized) ----------
__device__ __half g_xnh[MAXN * W];
__device__ __half g_aggh[MAXN * W];
__device__ __half g_h1h[MAXN * W];
__device__ __half g_wh[2 * 128 * 256];
__device__ float g_sum[G * W];        // self-cleaned by finalize
__device__ float g_sumsq[G * W];      // self-cleaned by finalize
__device__ float g_cnt[G];            // self-cleaned by finalize
__device__ float g_alpha[G * W];
__device__ float g_beta[G * W];
__device__ int   g_deg[MAXN];         // self-cleaned by scan3
__device__ int   g_base[MAXN + 4];
__device__ int   g_cur[MAXN];         // self-cleaned by gather
__device__ int2  g_elist[MAXE];
__device__ int   g_bsum[64];

// ---------------- PTX helpers (sm_80/90 baseline only) -----------------------
__device__ __forceinline__ uint32_t smem_u32(const void* p) {
    uint32_t a;
    asm("{ .reg .u64 t; cvta.to.shared.u64 t, %1; cvt.u32.u64 %0, t; }"
        : "=r"(a) : "l"(p));
    return a;
}
__device__ __forceinline__ void ldsm4(uint4& r, uint32_t addr) {
    asm volatile("ldmatrix.sync.aligned.m8n8.x4.shared.b16 {%0,%1,%2,%3}, [%4];"
                 : "=r"(r.x), "=r"(r.y), "=r"(r.z), "=r"(r.w) : "r"(addr));
}
__device__ __forceinline__ void mma16816(float* d, const uint4& a,
                                         uint32_t b0, uint32_t b1) {
    asm volatile(
        "mma.sync.aligned.m16n8k16.row.col.f32.f16.f16.f32 "
        "{%0,%1,%2,%3}, {%4,%5,%6,%7}, {%8,%9}, {%0,%1,%2,%3};"
        : "+f"(d[0]), "+f"(d[1]), "+f"(d[2]), "+f"(d[3])
        : "r"(a.x), "r"(a.y), "r"(a.z), "r"(a.w), "r"(b0), "r"(b1));
}
__device__ __forceinline__ void cp16(uint32_t dst, const void* src, bool pred) {
    int sz = pred ? 16 : 0;
    asm volatile("cp.async.cg.shared.global [%0], [%1], 16, %2;"
                 :: "r"(dst), "l"(src), "r"(sz) : "memory");
}
#define CP_COMMIT() asm volatile("cp.async.commit_group;" ::: "memory")
#define CP_WAIT(N)  asm volatile("cp.async.wait_group %0;" :: "n"(N) : "memory")

// ================= K1: stats || hist || wprep (grid-partitioned) =============
__global__ __launch_bounds__(256) void k1_kernel(
    const float* __restrict__ x, const int* __restrict__ bmap, int n,
    const int* __restrict__ dst, int E,
    const float* __restrict__ Wr1, const float* __restrict__ Wo1,
    const float* __restrict__ Wr2, const float* __restrict__ Wo2,
    int nbS, int nbH)
{
    int b = blockIdx.x, tid = threadIdx.x;
    if (b < nbS) {
        int f = tid & 127, sub = tid >> 7;
        int n0 = b * 256 + sub * 128;
        if (n0 >= n) return;
        int n1 = min(n0 + 128, n);
        float s = 0.f, ss = 0.f;
        int curg = __ldg(bmap + n0);
        int r = n0;
        // 8-row unrolled: loads issued before group checks (MLP 8)
        #pragma unroll 1
        for (; r + 8 <= n1; r += 8) {
            int gg[8];
            float vv[8];
            #pragma unroll
            for (int k = 0; k < 8; k++) gg[k] = __ldg(bmap + r + k);
            #pragma unroll
            for (int k = 0; k < 8; k++) vv[k] = x[(size_t)(r + k) * W + f];
            #pragma unroll
            for (int k = 0; k < 8; k++) {
                if (gg[k] != curg) {
                    atomicAdd(&g_sum[curg * W + f], s);
                    atomicAdd(&g_sumsq[curg * W + f], ss);
                    s = 0.f; ss = 0.f; curg = gg[k];
                }
                s += vv[k]; ss += vv[k] * vv[k];
            }
        }
        #pragma unroll 1
        for (; r < n1; r++) {
            int g = __ldg(bmap + r);
            if (g != curg) {
                atomicAdd(&g_sum[curg * W + f], s);
                atomicAdd(&g_sumsq[curg * W + f], ss);
                s = 0.f; ss = 0.f; curg = g;
            }
            float v = x[(size_t)r * W + f];
            s += v; ss += v * v;
        }
        atomicAdd(&g_sum[curg * W + f], s);
        atomicAdd(&g_sumsq[curg * W + f], ss);
        if (f == 0) {
            int cg = __ldg(bmap + n0), rs = n0;
            for (int rr = n0; rr < n1; rr++) {
                int g = __ldg(bmap + rr);
                if (g != cg) {
                    atomicAdd(&g_cnt[cg], (float)(rr - rs));
                    cg = g; rs = rr;
                }
            }
            atomicAdd(&g_cnt[cg], (float)(n1 - rs));
        }
    } else if (b < nbS + nbH) {
        int i4 = (b - nbS) * 256 + tid;
        int e = i4 * 4;
        if (e + 3 < E) {
            int4 d = __ldg((const int4*)dst + i4);
            atomicAdd(&g_deg[d.x], 1);
            atomicAdd(&g_deg[d.y], 1);
            atomicAdd(&g_deg[d.z], 1);
            atomicAdd(&g_deg[d.w], 1);
        } else {
            for (int j2 = 0; j2 < 4; j2++)
                if (e + j2 < E) atomicAdd(&g_deg[__ldg(dst + e + j2)], 1);
        }
    } else {
        int idx = (b - nbS - nbH) * 256 + tid;
        int conv = idx >> 14;
        int rem  = idx & 16383;
        int row  = rem >> 7;
        int c2   = rem & 127;
        const float* Wr = conv ? Wr2 : Wr1;
        const float* Wo = conv ? Wo2 : Wo1;
        const float* s = (c2 < 64) ? (Wr + row * 128 + c2 * 2)
                                   : (Wo + row * 128 + (c2 - 64) * 2);
        float2 v = *(const float2*)s;
        ((__half2*)(g_wh + (size_t)conv * 128 * 256 + row * 256))[c2] =
            __floats2half2_rn(v.x, v.y);
    }
}

// ================= K2: finalize || scan1 =====================================
__global__ __launch_bounds__(256) void k2_kernel(
    const float* __restrict__ gnw, const float* __restrict__ gnb,
    const float* __restrict__ msc, int n4, int nbF)
{
    int b = blockIdx.x, tid = threadIdx.x, lane = tid & 31, wid = tid >> 5;
    if (b < nbF) {
        int idx = b * 256 + tid;
        int g = idx >> 7, f = idx & 127;
        float cnt  = g_cnt[g];
        float inv  = (cnt > 0.f) ? (1.f / cnt) : 0.f;
        float mean = g_sum[idx] * inv;
        float q    = g_sumsq[idx] * inv;
        g_sum[idx] = 0.f;
        g_sumsq[idx] = 0.f;
        float m    = __ldg(msc + f);
        float var  = q - mean * mean * m * (2.f - m);
        float istd = rsqrtf(var + EPS);
        float a    = __ldg(gnw + f) * istd;
        g_alpha[idx] = a;
        g_beta[idx]  = __ldg(gnb + f) - a * m * mean;
        __syncthreads();
        if (f == 0) g_cnt[g] = 0.f;
    } else {
        __shared__ int wS[8];
        int sb = b - nbF;
        const int4* dp = (const int4*)g_deg;
        int i4 = sb * 1024 + tid * 4;
        int s = 0;
        #pragma unroll
        for (int j2 = 0; j2 < 4; j2++) {
            if (i4 + j2 < n4) {
                int4 v = dp[i4 + j2];
                s += v.x + v.y + v.z + v.w;
            }
        }
        #pragma unroll
        for (int o = 16; o > 0; o >>= 1) s += __shfl_down_sync(~0u, s, o);
        if (lane == 0) wS[wid] = s;
        __syncthreads();
        if (tid == 0) {
            int t = 0;
            #pragma unroll
            for (int k = 0; k < 8; k++) t += wS[k];
            g_bsum[sb] = t;
        }
    }
}

// ================= K3: scan3 (with inline scan2 over g_bsum) =================
__global__ __launch_bounds__(256) void k3_kernel(int n4, int nscan, int n)
{
    __shared__ int wS[8];
    __shared__ int boff;
    int b = blockIdx.x, tid = threadIdx.x, lane = tid & 31, wid = tid >> 5;
    if (tid == 0) {
        int run = 0;
        for (int i = 0; i < b; i++) run += g_bsum[i];
        boff = run;
        if (b == 0) {
            int tot = 0;
            for (int i = 0; i < nscan; i++) tot += g_bsum[i];
            g_base[n] = tot;
        }
    }
    int4* dp = (int4*)g_deg;
    int i4 = b * 1024 + tid * 4;
    int4 v[4];
    int s = 0;
    #pragma unroll
    for (int j2 = 0; j2 < 4; j2++) {
        v[j2] = make_int4(0, 0, 0, 0);
        if (i4 + j2 < n4) {
            v[j2] = dp[i4 + j2];
            dp[i4 + j2] = make_int4(0, 0, 0, 0);
        }
        s += v[j2].x + v[j2].y + v[j2].z + v[j2].w;
    }
    int x = s;
    #pragma unroll
    for (int o = 1; o < 32; o <<= 1) {
        int y = __shfl_up_sync(~0u, x, o);
        if (lane >= o) x += y;
    }
    if (lane == 31) wS[wid] = x;
    __syncthreads();
    int woff = 0;
    #pragma unroll
    for (int k = 0; k < 8; k++)
        if (k < wid) woff += wS[k];
    int run = boff + woff + x - s;
    int4* bp = (int4*)g_base;
    #pragma unroll
    for (int j2 = 0; j2 < 4; j2++) {
        if (i4 + j2 < n4) {
            int4 o;
            o.x = run; run += v[j2].x;
            o.y = run; run += v[j2].y;
            o.z = run; run += v[j2].z;
            o.w = run; run += v[j2].w;
            bp[i4 + j2] = o;
        }
    }
}

// ================= K4: place || norm (norm 4x ILP, coalesced) ================
__global__ __launch_bounds__(256) void k4_kernel(
    const int* __restrict__ src, const int* __restrict__ dst,
    const float* __restrict__ ew, int E,
    const float4* __restrict__ x, const int* __restrict__ bmap, int total4,
    int nbP)
{
    int b = blockIdx.x, tid = threadIdx.x;
    if (b < nbP) {
        int i4 = b * 256 + tid;
        int e = i4 * 4;
        if (e + 3 < E) {
            int4 sv = __ldg((const int4*)src + i4);
            int4 dv = __ldg((const int4*)dst + i4);
            float4 wv = __ldg((const float4*)ew + i4);
            int p;
            p = g_base[dv.x] + atomicAdd(&g_cur[dv.x], 1);
            g_elist[p] = make_int2(sv.x, __float_as_int(wv.x));
            p = g_base[dv.y] + atomicAdd(&g_cur[dv.y], 1);
            g_elist[p] = make_int2(sv.y, __float_as_int(wv.y));
            p = g_base[dv.z] + atomicAdd(&g_cur[dv.z], 1);
            g_elist[p] = make_int2(sv.z, __float_as_int(wv.z));
            p = g_base[dv.w] + atomicAdd(&g_cur[dv.w], 1);
            g_elist[p] = make_int2(sv.w, __float_as_int(wv.w));
        } else {
            for (int j2 = 0; j2 < 4; j2++) {
                int ee = e + j2;
                if (ee < E) {
                    int d = __ldg(dst + ee);
                    int p = g_base[d] + atomicAdd(&g_cur[d], 1);
                    g_elist[p] = make_int2(__ldg(src + ee),
                                           __float_as_int(__ldg(ew + ee)));
                }
            }
        }
    } else {
        // norm: 4 block-strided float4s per thread — each load coalesced,
        // all 4 issued back-to-back (MLP 4)
        int tbase = (b - nbP) * 1024 + tid;
        float4 xv[4];
        #pragma unroll
        for (int k = 0; k < 4; k++) {
            int idx = tbase + k * 256;
            if (idx < total4) xv[k] = __ldg(x + idx);
        }
        #pragma unroll
        for (int k = 0; k < 4; k++) {
            int idx = tbase + k * 256;
            if (idx >= total4) continue;
            int r = idx >> 5, c = idx & 31;
            int g = __ldg(bmap + r);
            float4 a = ((const float4*)g_alpha)[g * 32 + c];
            float4 bb = ((const float4*)g_beta)[g * 32 + c];
            float ox = fmaf(a.x, xv[k].x, bb.x);
            float oy = fmaf(a.y, xv[k].y, bb.y);
            float oz = fmaf(a.z, xv[k].z, bb.z);
            float ow = fmaf(a.w, xv[k].w, bb.w);
            uint2 o;
            *(__half2*)&o.x = __floats2half2_rn(ox, oy);
            *(__half2*)&o.y = __floats2half2_rn(oz, ow);
            ((uint2*)g_xnh)[idx] = o;
        }
    }
}

// ---------------- gather: half-warp per row, uint4 loads, 4/2/1-edge ILP -----
__device__ __forceinline__ void gacc(float* acc, uint4 v, float w) {
    float2 p0 = __half22float2(*(__half2*)&v.x);
    float2 p1 = __half22float2(*(__half2*)&v.y);
    float2 p2 = __half22float2(*(__half2*)&v.z);
    float2 p3 = __half22float2(*(__half2*)&v.w);
    acc[0] = fmaf(w, p0.x, acc[0]); acc[1] = fmaf(w, p0.y, acc[1]);
    acc[2] = fmaf(w, p1.x, acc[2]); acc[3] = fmaf(w, p1.y, acc[3]);
    acc[4] = fmaf(w, p2.x, acc[4]); acc[5] = fmaf(w, p2.y, acc[5]);
    acc[6] = fmaf(w, p3.x, acc[6]); acc[7] = fmaf(w, p3.y, acc[7]);
}

__global__ __launch_bounds__(256) void gather_kernel(
    const uint4* __restrict__ in, uint4* __restrict__ agg, int n)
{
    int row = (blockIdx.x * 256 + threadIdx.x) >> 4;   // one half-warp per row
    if (row >= n) return;
    int c = threadIdx.x & 15;
    int b0 = g_base[row], b1 = g_base[row + 1];
    if (c == 0) g_cur[row] = 0;                        // self-clean for replay
    float acc[8];
    #pragma unroll
    for (int i = 0; i < 8; i++) acc[i] = 0.f;
    int e = b0;
    #pragma unroll 1
    for (; e + 4 <= b1; e += 4) {
        int2 s0 = __ldg(&g_elist[e]);
        int2 s1 = __ldg(&g_elist[e + 1]);
        int2 s2 = __ldg(&g_elist[e + 2]);
        int2 s3 = __ldg(&g_elist[e + 3]);
        uint4 v0 = __ldg(in + (size_t)s0.x * 16 + c);
        uint4 v1 = __ldg(in + (size_t)s1.x * 16 + c);
        uint4 v2 = __ldg(in + (size_t)s2.x * 16 + c);
        uint4 v3 = __ldg(in + (size_t)s3.x * 16 + c);
        gacc(acc, v0, __int_as_float(s0.y));
        gacc(acc, v1, __int_as_float(s1.y));
        gacc(acc, v2, __int_as_float(s2.y));
        gacc(acc, v3, __int_as_float(s3.y));
    }
    if (e + 2 <= b1) {
        int2 s0 = __ldg(&g_elist[e]);
        int2 s1 = __ldg(&g_elist[e + 1]);
        uint4 v0 = __ldg(in + (size_t)s0.x * 16 + c);
        uint4 v1 = __ldg(in + (size_t)s1.x * 16 + c);
        gacc(acc, v0, __int_as_float(s0.y));
        gacc(acc, v1, __int_as_float(s1.y));
        e += 2;
    }
    if (e < b1) {
        int2 s0 = __ldg(&g_elist[e]);
        uint4 v0 = __ldg(in + (size_t)s0.x * 16 + c);
        gacc(acc, v0, __int_as_float(s0.y));
    }
    uint4 o;
    *(__half2*)&o.x = __floats2half2_rn(acc[0], acc[1]);
    *(__half2*)&o.y = __floats2half2_rn(acc[2], acc[3]);
    *(__half2*)&o.z = __floats2half2_rn(acc[4], acc[5]);
    *(__half2*)&o.w = __floats2half2_rn(acc[6], acc[7]);
    agg[(size_t)row * 16 + c] = o;
}

// ---------------- fp16 warp-MMA GEMM, cp.async pipelined (round-9 config) ----
#define GB_A0   1024
#define GB_W    (GB_A0 + 3 * 16384)
#define GB_SMEM (GB_W + 65536)

__device__ __forceinline__ void cpA(uint32_t sbase, int buf, int tid, int r0,
                                    int n, int c,
                                    const __half* __restrict__ Arel,
                                    const __half* __restrict__ Aroot)
{
    const char* As = (const char*)((c < 2) ? Arel : Aroot);
    int off = (c & 1) * 128;
    #pragma unroll
    for (int i = 0; i < 4; i++) {
        int q = tid + i * 256;
        int row = q >> 3, u = q & 7;
        int gr = r0 + row;
        cp16(sbase + GB_A0 + buf * 16384 + row * 128 + (((u ^ (row & 7)) & 7) << 4),
             As + (size_t)gr * 256 + off + u * 16, gr < n);
    }
}

template <int MODE>
__global__ __launch_bounds__(256) void gemm_h_kernel(
    const __half* __restrict__ Arel, const __half* __restrict__ Aroot,
    const __half* __restrict__ wh, const float* __restrict__ brel,
    const float* __restrict__ resid, void* __restrict__ outv, int n)
{
    extern __shared__ char smem[];
    uint32_t sbase = smem_u32(smem);
    int tid = threadIdx.x, wid = tid >> 5, lane = tid & 31;
    int wm = wid & 3, wn = wid >> 2;
    int r0 = blockIdx.x * 128;

    if (tid < 128) ((float*)smem)[tid] = __ldg(brel + tid);

    #pragma unroll
    for (int i = 0; i < 16; i++) {
        int q = tid + i * 256;
        int row = q >> 5, uu = q & 31;
        int phys = (uu & 0x18) | ((uu ^ row) & 7);
        cp16(sbase + GB_W + row * 512 + phys * 16,
             (const char*)wh + (size_t)row * 512 + uu * 16, true);
    }
    cpA(sbase, 0, tid, r0, n, 0, Arel, Aroot);
    CP_COMMIT();
    cpA(sbase, 1, tid, r0, n, 1, Arel, Aroot);
    CP_COMMIT();

    float acc[2][8][4];
    #pragma unroll
    for (int t = 0; t < 2; t++)
        #pragma unroll
        for (int u = 0; u < 8; u++)
            #pragma unroll
            for (int v = 0; v < 4; v++) acc[t][u][v] = 0.f;

    int j = lane & 7, grp = lane >> 3;
    int a_row = wm * 32 + ((grp & 1) << 3) + j;
    int a_ub  = grp >> 1;
    int b_row = wn * 64 + (((grp >> 1) & 1) << 3) + j;
    int b_r7  = b_row & 7;
    int b_ub  = grp & 1;

    #pragma unroll 1
    for (int c = 0; c < 4; c++) {
        if (c < 3) { CP_WAIT(1); } else { CP_WAIT(0); }
        __syncthreads();
        if (c < 2) {
            cpA(sbase, (c + 2) % 3, tid, r0, n, c + 2, Arel, Aroot);
            CP_COMMIT();
        }
        uint32_t aB = sbase + GB_A0 + (uint32_t)(c % 3) * 16384;
        #pragma unroll
        for (int ks = 0; ks < 4; ks++) {
            uint4 af[2];
            #pragma unroll
            for (int t = 0; t < 2; t++) {
                int row = a_row + t * 16;
                int u = ks * 2 + a_ub;
                ldsm4(af[t], aB + row * 128 + (((u ^ (row & 7)) & 7) << 4));
            }
            uint4 bf[4];
            #pragma unroll
            for (int p = 0; p < 4; p++) {
                int row = b_row + p * 16;
                int uu = c * 8 + ks * 2 + b_ub;
                int phys = (uu & 0x18) | ((uu ^ b_r7) & 7);
                ldsm4(bf[p], sbase + GB_W + row * 512 + phys * 16);
            }
            #pragma unroll
            for (int t = 0; t < 2; t++)
                #pragma unroll
                for (int u = 0; u < 8; u++) {
                    int p = u >> 1;
                    uint32_t b0 = (u & 1) ? bf[p].z : bf[p].x;
                    uint32_t b1 = (u & 1) ? bf[p].w : bf[p].y;
                    mma16816(acc[t][u], af[t], b0, b1);
                }
        }
    }

    const float* bias = (const float*)smem;
    int rb = r0 + wm * 32 + (lane >> 2);
    int cb = wn * 64 + ((lane & 3) << 1);
    #pragma unroll
    for (int t = 0; t < 2; t++) {
        #pragma unroll
        for (int u = 0; u < 8; u++) {
            int cc = cb + u * 8;
            float b0v = bias[cc], b1v = bias[cc + 1];
            #pragma unroll
            for (int h = 0; h < 2; h++) {
                int r = rb + t * 16 + h * 8;
                if (r >= n) continue;
                float vx = acc[t][u][h * 2 + 0] + b0v;
                float vy = acc[t][u][h * 2 + 1] + b1v;
                if (MODE == 0) {
                    vx = (vx >= 0.f) ? vx : 0.1f * vx;
                    vy = (vy >= 0.f) ? vy : 0.1f * vy;
                    __half2* op = (__half2*)((__half*)outv + (size_t)r * W + cc);
                    *op = __floats2half2_rn(vx, vy);
                } else {
                    float2 rr = *(const float2*)(resid + (size_t)r * W + cc);
                    vx += rr.x; vy += rr.y;
                    *(float2*)((float*)outv + (size_t)r * W + cc) =
                        make_float2(vx, vy);
                }
            }
        }
    }
}

// ---------------- launch -----------------------------------------------------
extern "C" void kernel_launch(void* const* d_in, const int* in_sizes, int n_in,
                              void* d_out, int out_size)
{
    const float* x      = (const float*)d_in[0];
    const int*   eidx   = (const int*)d_in[1];
    const float* ew     = (const float*)d_in[2];
    const int*   bmap   = (const int*)d_in[3];
    const float* gnw    = (const float*)d_in[4];
    const float* gnb    = (const float*)d_in[5];
    const float* msc    = (const float*)d_in[6];
    const float* Wrel1  = (const float*)d_in[7];
    const float* brel1  = (const float*)d_in[8];
    const float* Wroot1 = (const float*)d_in[9];
    const float* Wrel2  = (const float*)d_in[10];
    const float* brel2  = (const float*)d_in[11];
    const float* Wroot2 = (const float*)d_in[12];
    float* out = (float*)d_out;

    int n = in_sizes[0] / W;
    int E = in_sizes[2];
    const int* src = eidx;
    const int* dst = eidx + E;

    void *p_xnh, *p_aggh, *p_h1h, *p_wh;
    cudaGetSymbolAddress(&p_xnh, g_xnh);
    cudaGetSymbolAddress(&p_aggh, g_aggh);
    cudaGetSymbolAddress(&p_h1h, g_h1h);
    cudaGetSymbolAddress(&p_wh, g_wh);
    __half* xnh  = (__half*)p_xnh;
    __half* aggh = (__half*)p_aggh;
    __half* h1h  = (__half*)p_h1h;
    __half* wh   = (__half*)p_wh;

    cudaFuncSetAttribute(gemm_h_kernel<0>,
                         cudaFuncAttributeMaxDynamicSharedMemorySize, GB_SMEM);
    cudaFuncSetAttribute(gemm_h_kernel<1>,
                         cudaFuncAttributeMaxDynamicSharedMemorySize, GB_SMEM);

    // K1: stats || hist || wprep
    int nbS = (n + 255) / 256;
    int nbH = (E + 1023) / 1024;
    int nbW = 128;
    k1_kernel<<<nbS + nbH + nbW, 256>>>(x, bmap, n, dst, E,
                                        Wrel1, Wroot1, Wrel2, Wroot2, nbS, nbH);

    // K2: finalize || scan1
    int n4 = (n + 3) / 4;
    int nscan = (n4 + 1023) / 1024;
    int nbF = (G * W) / 256;
    k2_kernel<<<nbF + nscan, 256>>>(gnw, gnb, msc, n4, nbF);

    // K3: scan3 (inline scan2)
    k3_kernel<<<nscan, 256>>>(n4, nscan, n);

    // K4: place || norm (norm 4x ILP, coalesced)
    int nbP = (E + 1023) / 1024;
    int total4 = n * 32;
    int nbN = (total4 + 1023) / 1024;
    k4_kernel<<<nbP + nbN, 256>>>(src, dst, ew, E,
                                  (const float4*)x, bmap, total4, nbP);

    // conv1: gather + GEMM(+LeakyReLU) -> fp16 h1
    int gwBlocks = (n * 16 + 255) / 256;
    gather_kernel<<<gwBlocks, 256>>>((const uint4*)xnh, (uint4*)aggh, n);
    int gBlocks = (n + 127) / 128;
    gemm_h_kernel<0><<<gBlocks, 256, GB_SMEM>>>(
        aggh, xnh, wh, brel1, nullptr, h1h, n);

    // conv2: gather + GEMM(+residual) -> fp32 out
    gather_kernel<<<gwBlocks, 256>>>((const uint4*)h1h, (uint4*)aggh, n);
    gemm_h_kernel<1><<<gBlocks, 256, GB_SMEM>>>(
        aggh, h1h, wh + 128 * 256, brel2, x, out, n);
}